// round 11
// baseline (speedup 1.0000x reference)
#include <cuda_runtime.h>
#include <cuda_bf16.h>
#include <cstdint>

typedef unsigned long long u64;

// Problem constants
#define TT 512
#define BB 32
#define EE 1024
#define HH 512
#define CC 24
#define NGATE 2048          // 4*HH
#define NPROJ 4096          // 2 dirs * 4H
#define MROWS (TT*BB)       // 16384

// -------------------- scratch (device globals; no allocation) --------------------
__device__ __nv_bfloat16 g_x_hi[MROWS * EE];
__device__ __nv_bfloat16 g_x_lo[MROWS * EE];
__device__ __nv_bfloat16 g_h0_hi[MROWS * 1024];
__device__ __nv_bfloat16 g_h0_lo[MROWS * 1024];
__device__ __nv_bfloat16 g_w_hi[2 * NPROJ * EE];
__device__ __nv_bfloat16 g_w_lo[2 * NPROJ * EE];
__device__ float g_inproj[MROWS * NPROJ];   // [t][b][dir*2048 + gate*512 + j]
__device__ float g_hout1[MROWS * 1024];     // layer-1 output [t][b][dir*512+j]
__device__ float g_h[2 * 2 * BB * HH];      // [parity][dir][b*H + j]
__device__ volatile unsigned g_flags[2][64];  // per-dir, per-block step flags
__device__ float g_crf_partial[BB];

// -------------------- PTX helpers --------------------
__device__ __forceinline__ uint32_t smem_u32(const void* p) {
    uint32_t a;
    asm("{ .reg .u64 t; cvta.to.shared.u64 t, %1; cvt.u32.u64 %0, t; }" : "=r"(a) : "l"(p));
    return a;
}

#define CP_ASYNC16(dst, src) \
    asm volatile("cp.async.cg.shared.global [%0], [%1], 16;" :: "r"(dst), "l"(src) : "memory")
#define CP_COMMIT() asm volatile("cp.async.commit_group;" ::: "memory")
#define CP_WAIT(n)  asm volatile("cp.async.wait_group %0;" :: "n"(n) : "memory")

#define MMA_BF16(d, a, b) \
    asm volatile("mma.sync.aligned.m16n8k16.row.col.f32.bf16.bf16.f32 " \
        "{%0,%1,%2,%3}, {%4,%5,%6,%7}, {%8,%9}, {%0,%1,%2,%3};" \
        : "+f"((d)[0]), "+f"((d)[1]), "+f"((d)[2]), "+f"((d)[3]) \
        : "r"((a)[0]), "r"((a)[1]), "r"((a)[2]), "r"((a)[3]), \
          "r"((b)[0]), "r"((b)[1]))

#define LDSM_X4(r0, r1, r2, r3, addr) \
    asm volatile("ldmatrix.sync.aligned.m8n8.x4.shared.b16 {%0,%1,%2,%3}, [%4];" \
        : "=r"(r0), "=r"(r1), "=r"(r2), "=r"(r3) : "r"(addr))

// packed f32x2 FMA
#define FMA2(acc, x, y) asm("fma.rn.f32x2 %0, %1, %2, %0;" : "+l"(acc) : "l"(x), "l"(y))
__device__ __forceinline__ float sum2(u64 a) {
    float x, y;
    asm("mov.b64 {%0, %1}, %2;" : "=f"(x), "=f"(y) : "l"(a));
    return x + y;
}

__device__ __forceinline__ uint32_t pack_hi2(float a, float b, float& ra, float& rb) {
    __nv_bfloat16 ha = __float2bfloat16(a), hb = __float2bfloat16(b);
    ra = a - __bfloat162float(ha);
    rb = b - __bfloat162float(hb);
    return (uint32_t)__bfloat16_as_ushort(ha) | ((uint32_t)__bfloat16_as_ushort(hb) << 16);
}
__device__ __forceinline__ uint32_t pack_lo2(float ra, float rb) {
    __nv_bfloat16 la = __float2bfloat16(ra), lb = __float2bfloat16(rb);
    return (uint32_t)__bfloat16_as_ushort(la) | ((uint32_t)__bfloat16_as_ushort(lb) << 16);
}

// fast, saturating activations (error ~2^-20; no Inf/NaN at extremes)
__device__ __forceinline__ float fast_sigmoid(float x) { return 1.f / (1.f + __expf(-x)); }
__device__ __forceinline__ float fast_tanh(float x)    { return 1.f - 2.f / (1.f + __expf(2.f * x)); }

// -------------------- embedding gather + split --------------------
__global__ void gather_split(const int* __restrict__ x, const float* __restrict__ emb) {
    int idx = blockIdx.x * blockDim.x + threadIdx.x;   // MROWS * 256
    int e4 = idx & 255;
    int tb = idx >> 8;
    int b = tb & 31, t = tb >> 5;
    int tok = x[b * TT + t];
    float4 v = ((const float4*)(emb + (size_t)tok * EE))[e4];
    float r0, r1, r2, r3;
    uint2 hi, lo;
    hi.x = pack_hi2(v.x, v.y, r0, r1);
    hi.y = pack_hi2(v.z, v.w, r2, r3);
    lo.x = pack_lo2(r0, r1);
    lo.y = pack_lo2(r2, r3);
    size_t dst = (size_t)tb * EE + e4 * 4;
    *(uint2*)(g_x_hi + dst) = hi;
    *(uint2*)(g_x_lo + dst) = lo;
}

// -------------------- weight split (both layers) --------------------
__global__ void wconv(const float* __restrict__ w_ih) {
    int idx = blockIdx.x * blockDim.x + threadIdx.x;   // 2*4096*1024/4
    float4 v = ((const float4*)w_ih)[idx];
    float r0, r1, r2, r3;
    uint2 hi, lo;
    hi.x = pack_hi2(v.x, v.y, r0, r1);
    hi.y = pack_hi2(v.z, v.w, r2, r3);
    lo.x = pack_lo2(r0, r1);
    lo.y = pack_lo2(r2, r3);
    size_t dst = (size_t)idx * 4;
    *(uint2*)(g_w_hi + dst) = hi;
    *(uint2*)(g_w_lo + dst) = lo;
}

// -------------------- tensor-core split-bf16 GEMM (R9 version: ldmatrix + 4-stage) ----
#define GP 24                       // smem row pitch in bf16 (48B, conflict-free, 16B aligned)
#define TILE_B (128 * GP * 2)       // 6144 bytes per tensor
#define STAGE_B (4 * TILE_B)        // 24576 bytes per stage
#define NSTAGE 4
#define GM_SMEM (NSTAGE * STAGE_B)  // 98304

__global__ __launch_bounds__(256, 1)
void gemm_mma(int layer, const float* __restrict__ b1, const float* __restrict__ b2) {
    extern __shared__ char gsm[];
    __shared__ float s_bias[128];

    const int tid = threadIdx.x;
    const int lane = tid & 31, wid = tid >> 5;
    const int wm = wid & 3, wn = wid >> 2;          // 4 m-warps x 2 n-warps
    const int g = lane >> 2, tq = lane & 3;
    const int m0 = blockIdx.y * 128, n0 = blockIdx.x * 128;

    const __nv_bfloat16* A_hi = layer ? g_h0_hi : g_x_hi;
    const __nv_bfloat16* A_lo = layer ? g_h0_lo : g_x_lo;
    const __nv_bfloat16* srcs[4];
    srcs[0] = A_hi + (size_t)m0 * 1024;
    srcs[1] = A_lo + (size_t)m0 * 1024;
    srcs[2] = g_w_hi + (size_t)layer * NPROJ * EE + (size_t)n0 * 1024;
    srcs[3] = g_w_lo + (size_t)layer * NPROJ * EE + (size_t)n0 * 1024;

    if (tid < 128) s_bias[tid] = b1[n0 + tid] + b2[n0 + tid];

    const uint32_t sb = smem_u32(gsm);
    const int row  = tid >> 1;
    const int half = tid & 1;

#define LOAD_STAGE(s, kc) do { \
        uint32_t _d = sb + (s) * STAGE_B + row * 48 + half * 16; \
        size_t _go = (size_t)row * 1024 + (size_t)(kc) * 16 + half * 8; \
        CP_ASYNC16(_d + 0 * TILE_B, srcs[0] + _go); \
        CP_ASYNC16(_d + 1 * TILE_B, srcs[1] + _go); \
        CP_ASYNC16(_d + 2 * TILE_B, srcs[2] + _go); \
        CP_ASYNC16(_d + 3 * TILE_B, srcs[3] + _go); \
        CP_COMMIT(); \
    } while (0)

    uint32_t offA[2], offB[4];
#pragma unroll
    for (int mi = 0; mi < 2; mi++)
        offA[mi] = ((wm * 32 + mi * 16 + (lane & 15)) * GP + (lane >> 4) * 8) * 2;
#pragma unroll
    for (int p = 0; p < 4; p++) {
        int nr = wn * 64 + p * 16;
        offB[p] = ((nr + ((lane >> 4) & 1) * 8 + (lane & 7)) * GP + ((lane >> 3) & 1) * 8) * 2;
    }

    float acc[2][8][4];
#pragma unroll
    for (int mi = 0; mi < 2; mi++)
#pragma unroll
        for (int ni = 0; ni < 8; ni++)
#pragma unroll
            for (int q = 0; q < 4; q++) acc[mi][ni][q] = 0.f;

    LOAD_STAGE(0, 0);
    LOAD_STAGE(1, 1);
    LOAD_STAGE(2, 2);

    for (int kc = 0; kc < 64; kc++) {
        const int s = kc & 3;
        if (kc < 62) CP_WAIT(2);
        else if (kc == 62) CP_WAIT(1);
        else CP_WAIT(0);
        __syncthreads();
        if (kc + 3 < 64) LOAD_STAGE((kc + 3) & 3, kc + 3);

        const uint32_t st = sb + s * STAGE_B;

        uint32_t a_hi[2][4], a_lo[2][4], b_hi[8][2], b_lo[8][2];
#pragma unroll
        for (int mi = 0; mi < 2; mi++) {
            LDSM_X4(a_hi[mi][0], a_hi[mi][1], a_hi[mi][2], a_hi[mi][3], st + 0 * TILE_B + offA[mi]);
            LDSM_X4(a_lo[mi][0], a_lo[mi][1], a_lo[mi][2], a_lo[mi][3], st + 1 * TILE_B + offA[mi]);
        }
#pragma unroll
        for (int p = 0; p < 4; p++) {
            LDSM_X4(b_hi[2 * p][0], b_hi[2 * p][1], b_hi[2 * p + 1][0], b_hi[2 * p + 1][1],
                    st + 2 * TILE_B + offB[p]);
            LDSM_X4(b_lo[2 * p][0], b_lo[2 * p][1], b_lo[2 * p + 1][0], b_lo[2 * p + 1][1],
                    st + 3 * TILE_B + offB[p]);
        }

#pragma unroll
        for (int mi = 0; mi < 2; mi++)
#pragma unroll
            for (int ni = 0; ni < 8; ni++) {
                MMA_BF16(acc[mi][ni], a_hi[mi], b_hi[ni]);
                MMA_BF16(acc[mi][ni], a_hi[mi], b_lo[ni]);
                MMA_BF16(acc[mi][ni], a_lo[mi], b_hi[ni]);
            }
    }

#pragma unroll
    for (int mi = 0; mi < 2; mi++) {
        int mg = m0 + wm * 32 + mi * 16 + g;
#pragma unroll
        for (int ni = 0; ni < 8; ni++) {
            int nl = wn * 64 + ni * 8 + tq * 2;
            int ng = n0 + nl;
            float2 v0, v1;
            v0.x = acc[mi][ni][0] + s_bias[nl];
            v0.y = acc[mi][ni][1] + s_bias[nl + 1];
            v1.x = acc[mi][ni][2] + s_bias[nl];
            v1.y = acc[mi][ni][3] + s_bias[nl + 1];
            *(float2*)(g_inproj + (size_t)mg * NPROJ + ng) = v0;
            *(float2*)(g_inproj + (size_t)(mg + 8) * NPROJ + ng) = v1;
        }
    }
#undef LOAD_STAGE
}

// -------------------- zero h state + reset flags --------------------
__global__ void zero_state_kernel() {
    int i = blockIdx.x * blockDim.x + threadIdx.x;
    if (i < 2 * 2 * BB * HH) g_h[i] = 0.f;
    if (i < 128) ((volatile unsigned*)g_flags)[i] = 0u;
}

// -------------------- persistent bi-LSTM layer kernel --------------------
#define L_SMEM_FLOATS (32*512 + 32*516 + 32*33)
#define L_SMEM_BYTES  (L_SMEM_FLOATS * 4)

__global__ __launch_bounds__(256, 1)
void lstm_layer_persist(const float* __restrict__ whh_l, int layer) {
    extern __shared__ float smem[];
    float* ws  = smem;                          // [row=g*8+jl][512]
    float* hs  = smem + 32 * 512;               // [b][516]
    float* ips = smem + 32 * 512 + 32 * 516;    // [row][33]

    const int dir = (int)blockIdx.x >> 6;
    const int jt  = (int)blockIdx.x & 63;
    const int tid = threadIdx.x;
    const int w   = tid >> 5;
    const int b   = tid & 31;
    const int j   = jt * 8 + w;

    const float* __restrict__ wbase = whh_l + (size_t)dir * 4 * HH * HH;

    for (int i = tid; i < 32 * 128; i += 256) {
        int rw = i >> 7, k4 = i & 127;
        int gg = rw >> 3, jl = rw & 7;
        float4 v = *(const float4*)(wbase + (size_t)(gg * HH + jt * 8 + jl) * HH + k4 * 4);
        *(float4*)(ws + rw * 512 + k4 * 4) = v;
    }
    __syncthreads();

    const int sb  = tid >> 3;
    const int sg  = (tid >> 1) & 3;
    const int sj4 = tid & 1;
    const float* ipg_base = g_inproj + sb * NPROJ + dir * NGATE + sg * HH + jt * 8 + sj4 * 4;

    float c_reg = 0.f;

    for (int t = 0; t < TT; t++) {
        const int p  = t & 1;
        const int tt = dir ? (TT - 1 - t) : t;

        // prefetch step-invariant input projection BEFORE the barrier
        float4 ipv = *(const float4*)(ipg_base + (size_t)tt * 32 * NPROJ);

        if (t > 0) {
            __syncthreads();                      // all warps' h stores issued
            if (tid == 0) {
                __threadfence();                  // publish my h(t-1) (cumulative)
                g_flags[dir][jt] = (unsigned)t;   // release my flag
            }
            if (tid < 32) {
                // poll all 64 producer flags of this direction
                while (true) {
                    unsigned a = g_flags[dir][tid];
                    unsigned c = g_flags[dir][tid + 32];
                    if (!__any_sync(0xffffffffu,
                                    (a < (unsigned)t) || (c < (unsigned)t))) break;
                }
                __threadfence();                  // acquire
            }
            __syncthreads();
        }

        {
            const float* hsrc = g_h + (size_t)(p * 2 + dir) * (BB * HH);
            for (int i = tid; i < 32 * 128; i += 256) {
                int bb = i >> 7, k4 = i & 127;
                float4 v = *(const float4*)(hsrc + bb * 512 + k4 * 4);
                *(float4*)(hs + bb * 516 + k4 * 4) = v;
            }
        }
        {
            int rbase = sg * 8 + sj4 * 4;
            ips[(rbase + 0) * 33 + sb] = ipv.x;
            ips[(rbase + 1) * 33 + sb] = ipv.y;
            ips[(rbase + 2) * 33 + sb] = ipv.z;
            ips[(rbase + 3) * 33 + sb] = ipv.w;
        }
        __syncthreads();

        const ulonglong2* hp  = (const ulonglong2*)(hs + b * 516);
        const ulonglong2* w0p = (const ulonglong2*)(ws + (0 * 8 + w) * 512);
        const ulonglong2* w1p = (const ulonglong2*)(ws + (1 * 8 + w) * 512);
        const ulonglong2* w2p = (const ulonglong2*)(ws + (2 * 8 + w) * 512);
        const ulonglong2* w3p = (const ulonglong2*)(ws + (3 * 8 + w) * 512);

        u64 ac0 = 0, ac1 = 0, ac2 = 0, ac3 = 0, ac4 = 0, ac5 = 0, ac6 = 0, ac7 = 0;
#pragma unroll 8
        for (int k4 = 0; k4 < 128; k4++) {
            ulonglong2 h2 = hp[k4];
            ulonglong2 q0 = w0p[k4];
            ulonglong2 q1 = w1p[k4];
            ulonglong2 q2 = w2p[k4];
            ulonglong2 q3 = w3p[k4];
            FMA2(ac0, h2.x, q0.x);  FMA2(ac1, h2.y, q0.y);
            FMA2(ac2, h2.x, q1.x);  FMA2(ac3, h2.y, q1.y);
            FMA2(ac4, h2.x, q2.x);  FMA2(ac5, h2.y, q2.y);
            FMA2(ac6, h2.x, q3.x);  FMA2(ac7, h2.y, q3.y);
        }

        float gi = sum2(ac0) + sum2(ac1) + ips[(0 * 8 + w) * 33 + b];
        float gf = sum2(ac2) + sum2(ac3) + ips[(1 * 8 + w) * 33 + b];
        float gg = sum2(ac4) + sum2(ac5) + ips[(2 * 8 + w) * 33 + b];
        float go = sum2(ac6) + sum2(ac7) + ips[(3 * 8 + w) * 33 + b];

        gi = fast_sigmoid(gi);
        gf = fast_sigmoid(gf);
        gg = fast_tanh(gg);
        go = fast_sigmoid(go);

        c_reg = gf * c_reg + gi * gg;
        float h = go * fast_tanh(c_reg);

        g_h[(size_t)((p ^ 1) * 2 + dir) * (BB * HH) + b * 512 + j] = h;

        size_t o = ((size_t)tt * 32 + b) * 1024 + dir * HH + j;
        if (layer == 0) {
            __nv_bfloat16 hh = __float2bfloat16(h);
            __nv_bfloat16 hl = __float2bfloat16(h - __bfloat162float(hh));
            g_h0_hi[o] = hh;
            g_h0_lo[o] = hl;
        } else {
            g_hout1[o] = h;
        }
    }
}

// -------------------- FC: logits[b][t][c] --------------------
__global__ void fc_kernel(const float* __restrict__ fcw, const float* __restrict__ fcb,
                          float* __restrict__ out) {
    int row = blockIdx.x;          // t*BB + b
    int t = row >> 5;
    int b = row & 31;
    int c = threadIdx.x >> 5;      // 0..23
    int lane = threadIdx.x & 31;

    const float4* h4 = (const float4*)(g_hout1 + (size_t)row * 1024);
    const float4* w4 = (const float4*)(fcw + (size_t)c * 1024);
    float s = 0.f;
#pragma unroll 4
    for (int k = lane; k < 256; k += 32) {
        float4 a = h4[k], w = w4[k];
        s += a.x * w.x + a.y * w.y + a.z * w.z + a.w * w.w;
    }
#pragma unroll
    for (int o = 16; o; o >>= 1) s += __shfl_xor_sync(0xffffffffu, s, o);
    if (lane == 0) out[((size_t)b * TT + t) * CC + c] = s + fcb[c];
}

// -------------------- CRF per-batch block --------------------
__global__ void crf_block(const float* __restrict__ em, const int* __restrict__ labels,
                          const float* __restrict__ st, const float* __restrict__ en,
                          const float* __restrict__ tr) {
    const int b = blockIdx.x;
    const int cn = threadIdx.x;    // 32 threads, 24 active for DP
    __shared__ float trs[24][25];
    __shared__ float alpha[25];
    __shared__ int   labs[TT];
    __shared__ float s_en[24], s_st[24];

    for (int i = cn; i < 576; i += 32) trs[i / 24][i % 24] = tr[i];
    if (cn < 24) { s_en[cn] = en[cn]; s_st[cn] = st[cn]; }
    for (int i = cn; i < TT; i += 32) labs[i] = labels[b * TT + i];
    __syncwarp();

    const float* emb_ = em + (size_t)b * TT * CC;
    if (cn < 24) alpha[cn] = s_st[cn] + emb_[cn];
    __syncwarp();

    for (int t = 1; t < TT; t++) {
        float anew = 0.f;
        if (cn < 24) {
            float m = -1e30f;
#pragma unroll
            for (int cp = 0; cp < 24; cp++) m = fmaxf(m, alpha[cp] + trs[cp][cn]);
            float s = 0.f;
#pragma unroll
            for (int cp = 0; cp < 24; cp++) s += __expf(alpha[cp] + trs[cp][cn] - m);
            anew = m + __logf(s) + emb_[t * CC + cn];
        }
        __syncwarp();
        if (cn < 24) alpha[cn] = anew;
        __syncwarp();
    }

    float gs = 0.f;
    for (int t = cn; t < TT; t += 32) {
        int tg = labs[t];
        gs += emb_[t * CC + tg];
        if (t > 0) gs += trs[labs[t - 1]][tg];
    }
#pragma unroll
    for (int o = 16; o; o >>= 1) gs += __shfl_xor_sync(0xffffffffu, gs, o);

    if (cn == 0) {
        float m = -1e30f;
        for (int c = 0; c < 24; c++) m = fmaxf(m, alpha[c] + s_en[c]);
        float s = 0.f;
        for (int c = 0; c < 24; c++) s += __expf(alpha[c] + s_en[c] - m);
        float logZ = m + __logf(s);
        float num = gs + s_st[labs[0]] + s_en[labs[TT - 1]];
        g_crf_partial[b] = logZ - num;
    }
}

__global__ void crf_final(float* __restrict__ loss_out) {
    if (threadIdx.x == 0) {
        float L = 0.f;
        for (int b = 0; b < BB; b++) L += g_crf_partial[b];
        loss_out[0] = L;   // -llh
    }
}

// -------------------- launch --------------------
extern "C" void kernel_launch(void* const* d_in, const int* in_sizes, int n_in,
                              void* d_out, int out_size) {
    const int*   x         = (const int*)d_in[0];
    const int*   labels    = (const int*)d_in[1];
    const float* emb       = (const float*)d_in[2];
    const float* w_ih      = (const float*)d_in[3];
    const float* w_hh      = (const float*)d_in[4];
    const float* b_ih      = (const float*)d_in[5];
    const float* b_hh      = (const float*)d_in[6];
    const float* fc_w      = (const float*)d_in[7];
    const float* fc_b      = (const float*)d_in[8];
    const float* crf_start = (const float*)d_in[9];
    const float* crf_end   = (const float*)d_in[10];
    const float* crf_trans = (const float*)d_in[11];
    float* out = (float*)d_out;

    (void)in_sizes; (void)n_in; (void)out_size;

    cudaFuncSetAttribute(lstm_layer_persist,
                         cudaFuncAttributeMaxDynamicSharedMemorySize, L_SMEM_BYTES);
    cudaFuncSetAttribute(gemm_mma,
                         cudaFuncAttributeMaxDynamicSharedMemorySize, GM_SMEM);

    // 1. embedding gather + bf16 split
    gather_split<<<MROWS, 256>>>(x, emb);

    // 2. weight split (both layers)
    wconv<<<8192, 256>>>(w_ih);

    // 3. per-layer: tensor-core input projection, then persistent recurrence
    for (int l = 0; l < 2; l++) {
        const float* whh_l = w_hh + (size_t)l * 2 * NGATE * HH;
        const float* bih_l = b_ih + (size_t)l * NPROJ;
        const float* bhh_l = b_hh + (size_t)l * NPROJ;

        gemm_mma<<<dim3(NPROJ / 128, MROWS / 128), 256, GM_SMEM>>>(l, bih_l, bhh_l);
        zero_state_kernel<<<256, 256>>>();
        lstm_layer_persist<<<128, 256, L_SMEM_BYTES>>>(whh_l, l);
    }

    // 4. FC -> logits into d_out as [b][t][c]
    fc_kernel<<<MROWS, 768>>>(fc_w, fc_b, out);

    // 5. CRF loss -> d_out[B*T*C]
    crf_block<<<BB, 32>>>(out, labels, crf_start, crf_end, crf_trans);
    crf_final<<<1, 32>>>(out + (size_t)BB * TT * CC);
}

// round 12
// speedup vs baseline: 1.2903x; 1.2903x over previous
#include <cuda_runtime.h>
#include <cuda_bf16.h>
#include <cstdint>

typedef unsigned long long u64;

// Problem constants
#define TT 512
#define BB 32
#define EE 1024
#define HH 512
#define CC 24
#define NGATE 2048          // 4*HH
#define NPROJ 4096          // 2 dirs * 4H
#define MROWS (TT*BB)       // 16384

// -------------------- scratch (device globals; no allocation) --------------------
__device__ __nv_bfloat16 g_x_hi[MROWS * EE];
__device__ __nv_bfloat16 g_x_lo[MROWS * EE];
__device__ __nv_bfloat16 g_h0_hi[MROWS * 1024];
__device__ __nv_bfloat16 g_h0_lo[MROWS * 1024];
__device__ __nv_bfloat16 g_w_hi[2 * NPROJ * EE];
__device__ __nv_bfloat16 g_w_lo[2 * NPROJ * EE];
__device__ float g_inproj[MROWS * NPROJ];   // [t][b][dir*2048 + gate*512 + j]
__device__ float g_hout1[MROWS * 1024];     // layer-1 output [t][b][dir*512+j]
__device__ float g_h[2 * 2 * BB * HH];      // [parity][dir][b*H + j]
__device__ unsigned g_bar_cnt[2];
__device__ unsigned g_bar_gen[2];
__device__ float g_crf_partial[BB];

// -------------------- PTX helpers --------------------
__device__ __forceinline__ uint32_t smem_u32(const void* p) {
    uint32_t a;
    asm("{ .reg .u64 t; cvta.to.shared.u64 t, %1; cvt.u32.u64 %0, t; }" : "=r"(a) : "l"(p));
    return a;
}

#define CP_ASYNC16(dst, src) \
    asm volatile("cp.async.cg.shared.global [%0], [%1], 16;" :: "r"(dst), "l"(src) : "memory")
#define CP_COMMIT() asm volatile("cp.async.commit_group;" ::: "memory")
#define CP_WAIT(n)  asm volatile("cp.async.wait_group %0;" :: "n"(n) : "memory")

#define MMA_BF16(d, a, b) \
    asm volatile("mma.sync.aligned.m16n8k16.row.col.f32.bf16.bf16.f32 " \
        "{%0,%1,%2,%3}, {%4,%5,%6,%7}, {%8,%9}, {%0,%1,%2,%3};" \
        : "+f"((d)[0]), "+f"((d)[1]), "+f"((d)[2]), "+f"((d)[3]) \
        : "r"((a)[0]), "r"((a)[1]), "r"((a)[2]), "r"((a)[3]), \
          "r"((b)[0]), "r"((b)[1]))

#define LDSM_X4(r0, r1, r2, r3, addr) \
    asm volatile("ldmatrix.sync.aligned.m8n8.x4.shared.b16 {%0,%1,%2,%3}, [%4];" \
        : "=r"(r0), "=r"(r1), "=r"(r2), "=r"(r3) : "r"(addr))

// packed f32x2 FMA
#define FMA2(acc, x, y) asm("fma.rn.f32x2 %0, %1, %2, %0;" : "+l"(acc) : "l"(x), "l"(y))
__device__ __forceinline__ float sum2(u64 a) {
    float x, y;
    asm("mov.b64 {%0, %1}, %2;" : "=f"(x), "=f"(y) : "l"(a));
    return x + y;
}

__device__ __forceinline__ uint32_t pack_hi2(float a, float b, float& ra, float& rb) {
    __nv_bfloat16 ha = __float2bfloat16(a), hb = __float2bfloat16(b);
    ra = a - __bfloat162float(ha);
    rb = b - __bfloat162float(hb);
    return (uint32_t)__bfloat16_as_ushort(ha) | ((uint32_t)__bfloat16_as_ushort(hb) << 16);
}
__device__ __forceinline__ uint32_t pack_lo2(float ra, float rb) {
    __nv_bfloat16 la = __float2bfloat16(ra), lb = __float2bfloat16(rb);
    return (uint32_t)__bfloat16_as_ushort(la) | ((uint32_t)__bfloat16_as_ushort(lb) << 16);
}

// fast, saturating activations (error ~2^-20; no Inf/NaN at extremes)
__device__ __forceinline__ float fast_sigmoid(float x) { return 1.f / (1.f + __expf(-x)); }
__device__ __forceinline__ float fast_tanh(float x)    { return 1.f - 2.f / (1.f + __expf(2.f * x)); }

// -------------------- embedding gather + split --------------------
__global__ void gather_split(const int* __restrict__ x, const float* __restrict__ emb) {
    int idx = blockIdx.x * blockDim.x + threadIdx.x;   // MROWS * 256
    int e4 = idx & 255;
    int tb = idx >> 8;
    int b = tb & 31, t = tb >> 5;
    int tok = x[b * TT + t];
    float4 v = ((const float4*)(emb + (size_t)tok * EE))[e4];
    float r0, r1, r2, r3;
    uint2 hi, lo;
    hi.x = pack_hi2(v.x, v.y, r0, r1);
    hi.y = pack_hi2(v.z, v.w, r2, r3);
    lo.x = pack_lo2(r0, r1);
    lo.y = pack_lo2(r2, r3);
    size_t dst = (size_t)tb * EE + e4 * 4;
    *(uint2*)(g_x_hi + dst) = hi;
    *(uint2*)(g_x_lo + dst) = lo;
}

// -------------------- weight split (both layers) --------------------
__global__ void wconv(const float* __restrict__ w_ih) {
    int idx = blockIdx.x * blockDim.x + threadIdx.x;   // 2*4096*1024/4
    float4 v = ((const float4*)w_ih)[idx];
    float r0, r1, r2, r3;
    uint2 hi, lo;
    hi.x = pack_hi2(v.x, v.y, r0, r1);
    hi.y = pack_hi2(v.z, v.w, r2, r3);
    lo.x = pack_lo2(r0, r1);
    lo.y = pack_lo2(r2, r3);
    size_t dst = (size_t)idx * 4;
    *(uint2*)(g_w_hi + dst) = hi;
    *(uint2*)(g_w_lo + dst) = lo;
}

// -------------------- tensor-core split-bf16 GEMM (R9: ldmatrix + 4-stage) ----
#define GP 24                       // smem row pitch in bf16
#define TILE_B (128 * GP * 2)       // 6144 bytes per tensor
#define STAGE_B (4 * TILE_B)        // 24576 bytes per stage
#define NSTAGE 4
#define GM_SMEM (NSTAGE * STAGE_B)  // 98304

__global__ __launch_bounds__(256, 1)
void gemm_mma(int layer, const float* __restrict__ b1, const float* __restrict__ b2) {
    extern __shared__ char gsm[];
    __shared__ float s_bias[128];

    const int tid = threadIdx.x;
    const int lane = tid & 31, wid = tid >> 5;
    const int wm = wid & 3, wn = wid >> 2;
    const int g = lane >> 2, tq = lane & 3;
    const int m0 = blockIdx.y * 128, n0 = blockIdx.x * 128;

    const __nv_bfloat16* A_hi = layer ? g_h0_hi : g_x_hi;
    const __nv_bfloat16* A_lo = layer ? g_h0_lo : g_x_lo;
    const __nv_bfloat16* srcs[4];
    srcs[0] = A_hi + (size_t)m0 * 1024;
    srcs[1] = A_lo + (size_t)m0 * 1024;
    srcs[2] = g_w_hi + (size_t)layer * NPROJ * EE + (size_t)n0 * 1024;
    srcs[3] = g_w_lo + (size_t)layer * NPROJ * EE + (size_t)n0 * 1024;

    if (tid < 128) s_bias[tid] = b1[n0 + tid] + b2[n0 + tid];

    const uint32_t sb = smem_u32(gsm);
    const int row  = tid >> 1;
    const int half = tid & 1;

#define LOAD_STAGE(s, kc) do { \
        uint32_t _d = sb + (s) * STAGE_B + row * 48 + half * 16; \
        size_t _go = (size_t)row * 1024 + (size_t)(kc) * 16 + half * 8; \
        CP_ASYNC16(_d + 0 * TILE_B, srcs[0] + _go); \
        CP_ASYNC16(_d + 1 * TILE_B, srcs[1] + _go); \
        CP_ASYNC16(_d + 2 * TILE_B, srcs[2] + _go); \
        CP_ASYNC16(_d + 3 * TILE_B, srcs[3] + _go); \
        CP_COMMIT(); \
    } while (0)

    uint32_t offA[2], offB[4];
#pragma unroll
    for (int mi = 0; mi < 2; mi++)
        offA[mi] = ((wm * 32 + mi * 16 + (lane & 15)) * GP + (lane >> 4) * 8) * 2;
#pragma unroll
    for (int p = 0; p < 4; p++) {
        int nr = wn * 64 + p * 16;
        offB[p] = ((nr + ((lane >> 4) & 1) * 8 + (lane & 7)) * GP + ((lane >> 3) & 1) * 8) * 2;
    }

    float acc[2][8][4];
#pragma unroll
    for (int mi = 0; mi < 2; mi++)
#pragma unroll
        for (int ni = 0; ni < 8; ni++)
#pragma unroll
            for (int q = 0; q < 4; q++) acc[mi][ni][q] = 0.f;

    LOAD_STAGE(0, 0);
    LOAD_STAGE(1, 1);
    LOAD_STAGE(2, 2);

    for (int kc = 0; kc < 64; kc++) {
        const int s = kc & 3;
        if (kc < 62) CP_WAIT(2);
        else if (kc == 62) CP_WAIT(1);
        else CP_WAIT(0);
        __syncthreads();
        if (kc + 3 < 64) LOAD_STAGE((kc + 3) & 3, kc + 3);

        const uint32_t st = sb + s * STAGE_B;

        uint32_t a_hi[2][4], a_lo[2][4], b_hi[8][2], b_lo[8][2];
#pragma unroll
        for (int mi = 0; mi < 2; mi++) {
            LDSM_X4(a_hi[mi][0], a_hi[mi][1], a_hi[mi][2], a_hi[mi][3], st + 0 * TILE_B + offA[mi]);
            LDSM_X4(a_lo[mi][0], a_lo[mi][1], a_lo[mi][2], a_lo[mi][3], st + 1 * TILE_B + offA[mi]);
        }
#pragma unroll
        for (int p = 0; p < 4; p++) {
            LDSM_X4(b_hi[2 * p][0], b_hi[2 * p][1], b_hi[2 * p + 1][0], b_hi[2 * p + 1][1],
                    st + 2 * TILE_B + offB[p]);
            LDSM_X4(b_lo[2 * p][0], b_lo[2 * p][1], b_lo[2 * p + 1][0], b_lo[2 * p + 1][1],
                    st + 3 * TILE_B + offB[p]);
        }

#pragma unroll
        for (int mi = 0; mi < 2; mi++)
#pragma unroll
            for (int ni = 0; ni < 8; ni++) {
                MMA_BF16(acc[mi][ni], a_hi[mi], b_hi[ni]);
                MMA_BF16(acc[mi][ni], a_hi[mi], b_lo[ni]);
                MMA_BF16(acc[mi][ni], a_lo[mi], b_hi[ni]);
            }
    }

#pragma unroll
    for (int mi = 0; mi < 2; mi++) {
        int mg = m0 + wm * 32 + mi * 16 + g;
#pragma unroll
        for (int ni = 0; ni < 8; ni++) {
            int nl = wn * 64 + ni * 8 + tq * 2;
            int ng = n0 + nl;
            float2 v0, v1;
            v0.x = acc[mi][ni][0] + s_bias[nl];
            v0.y = acc[mi][ni][1] + s_bias[nl + 1];
            v1.x = acc[mi][ni][2] + s_bias[nl];
            v1.y = acc[mi][ni][3] + s_bias[nl + 1];
            *(float2*)(g_inproj + (size_t)mg * NPROJ + ng) = v0;
            *(float2*)(g_inproj + (size_t)(mg + 8) * NPROJ + ng) = v1;
        }
    }
#undef LOAD_STAGE
}

// -------------------- zero h state + reset barriers --------------------
__global__ void zero_state_kernel() {
    int i = blockIdx.x * blockDim.x + threadIdx.x;
    if (i < 2 * 2 * BB * HH) g_h[i] = 0.f;
    if (i < 2) { g_bar_cnt[i] = 0u; g_bar_gen[i] = 0u; }
}

// -------------------- persistent bi-LSTM layer kernel --------------------
// 128 threads = 4 warps (1/SMSP); warp w4 owns 2 j-rows; lane = batch.
// h LDS halved vs 256-thread layout (each h load feeds 2j x 4g = 16 FMA2).
#define L_SMEM_FLOATS (32*512 + 32*516 + 32*33)
#define L_SMEM_BYTES  (L_SMEM_FLOATS * 4)

__global__ __launch_bounds__(128, 1)
void lstm_layer_persist(const float* __restrict__ whh_l, int layer) {
    extern __shared__ float smem[];
    float* ws  = smem;                          // [row=g*8+jl][512]
    float* hs  = smem + 32 * 512;               // [b][516]
    float* ips = smem + 32 * 512 + 32 * 516;    // [row][33]

    const int dir = (int)blockIdx.x >> 6;
    const int jt  = (int)blockIdx.x & 63;
    const int tid = threadIdx.x;
    const int w4  = tid >> 5;             // warp 0..3 -> j-pair
    const int b   = tid & 31;             // lane -> batch
    const int jl0 = 2 * w4;               // local j of jj=0
    const int j0  = jt * 8 + jl0;

    const float* __restrict__ wbase = whh_l + (size_t)dir * 4 * HH * HH;

    // load Whh slice once: row r = g*8+jl  <-  whh row g*512 + jt*8 + jl
    for (int i = tid; i < 32 * 128; i += 128) {
        int rw = i >> 7, k4 = i & 127;
        int gg = rw >> 3, jl = rw & 7;
        float4 v = *(const float4*)(wbase + (size_t)(gg * HH + jt * 8 + jl) * HH + k4 * 4);
        *(float4*)(ws + rw * 512 + k4 * 4) = v;
    }
    __syncthreads();

    // ip staging: thread(sb=b, sg=w4) loads rows sg*8..sg*8+7 for batch sb
    const int sb = b;
    const int sg = w4;
    const float* ipg_base = g_inproj + sb * NPROJ + dir * NGATE + sg * HH + jt * 8;

    float c0 = 0.f, c1 = 0.f;

    for (int t = 0; t < TT; t++) {
        const int p  = t & 1;
        const int tt = dir ? (TT - 1 - t) : t;

        // prefetch step-invariant input projection BEFORE the barrier
        const float* ipg = ipg_base + (size_t)tt * 32 * NPROJ;
        float4 ipv0 = *(const float4*)(ipg);
        float4 ipv1 = *(const float4*)(ipg + 4);

        if (t > 0) {
            __syncthreads();
            if (tid == 0) {
                __threadfence();
                unsigned a = atomicAdd(&g_bar_cnt[dir], 1u);
                if (a == 63u) {
                    g_bar_cnt[dir] = 0u;
                    __threadfence();
                    atomicExch(&g_bar_gen[dir], (unsigned)t);
                } else {
                    while (*(volatile unsigned*)&g_bar_gen[dir] < (unsigned)t) { }
                }
                __threadfence();
            }
            __syncthreads();
        }

        {
            const float* hsrc = g_h + (size_t)(p * 2 + dir) * (BB * HH);
            for (int i = tid; i < 32 * 128; i += 128) {
                int bb = i >> 7, k4 = i & 127;
                float4 v = *(const float4*)(hsrc + bb * 512 + k4 * 4);
                *(float4*)(hs + bb * 516 + k4 * 4) = v;
            }
        }
        {
            int rbase = sg * 8;
            ips[(rbase + 0) * 33 + sb] = ipv0.x;
            ips[(rbase + 1) * 33 + sb] = ipv0.y;
            ips[(rbase + 2) * 33 + sb] = ipv0.z;
            ips[(rbase + 3) * 33 + sb] = ipv0.w;
            ips[(rbase + 4) * 33 + sb] = ipv1.x;
            ips[(rbase + 5) * 33 + sb] = ipv1.y;
            ips[(rbase + 6) * 33 + sb] = ipv1.z;
            ips[(rbase + 7) * 33 + sb] = ipv1.w;
        }
        __syncthreads();

        const ulonglong2* hp = (const ulonglong2*)(hs + b * 516);
        const ulonglong2* wp[2][4];
#pragma unroll
        for (int jj = 0; jj < 2; jj++)
#pragma unroll
            for (int gg = 0; gg < 4; gg++)
                wp[jj][gg] = (const ulonglong2*)(ws + (gg * 8 + jl0 + jj) * 512);

        u64 ac[2][4][2];
#pragma unroll
        for (int jj = 0; jj < 2; jj++)
#pragma unroll
            for (int gg = 0; gg < 4; gg++) { ac[jj][gg][0] = 0; ac[jj][gg][1] = 0; }

#pragma unroll 4
        for (int k4 = 0; k4 < 128; k4++) {
            ulonglong2 h2 = hp[k4];
#pragma unroll
            for (int jj = 0; jj < 2; jj++) {
#pragma unroll
                for (int gg = 0; gg < 4; gg++) {
                    ulonglong2 q = wp[jj][gg][k4];
                    FMA2(ac[jj][gg][0], h2.x, q.x);
                    FMA2(ac[jj][gg][1], h2.y, q.y);
                }
            }
        }

        float* hdst = g_h + (size_t)((p ^ 1) * 2 + dir) * (BB * HH) + b * 512;
#pragma unroll
        for (int jj = 0; jj < 2; jj++) {
            int jl = jl0 + jj;
            float gi = sum2(ac[jj][0][0]) + sum2(ac[jj][0][1]) + ips[(0 * 8 + jl) * 33 + b];
            float gf = sum2(ac[jj][1][0]) + sum2(ac[jj][1][1]) + ips[(1 * 8 + jl) * 33 + b];
            float gg = sum2(ac[jj][2][0]) + sum2(ac[jj][2][1]) + ips[(2 * 8 + jl) * 33 + b];
            float go = sum2(ac[jj][3][0]) + sum2(ac[jj][3][1]) + ips[(3 * 8 + jl) * 33 + b];

            gi = fast_sigmoid(gi);
            gf = fast_sigmoid(gf);
            gg = fast_tanh(gg);
            go = fast_sigmoid(go);

            float c = jj ? c1 : c0;
            c = gf * c + gi * gg;
            if (jj) c1 = c; else c0 = c;
            float h = go * fast_tanh(c);

            hdst[j0 + jj] = h;

            size_t o = ((size_t)tt * 32 + b) * 1024 + dir * HH + j0 + jj;
            if (layer == 0) {
                __nv_bfloat16 hh = __float2bfloat16(h);
                __nv_bfloat16 hl = __float2bfloat16(h - __bfloat162float(hh));
                g_h0_hi[o] = hh;
                g_h0_lo[o] = hl;
            } else {
                g_hout1[o] = h;
            }
        }
    }
}

// -------------------- FC: logits[b][t][c] --------------------
__global__ void fc_kernel(const float* __restrict__ fcw, const float* __restrict__ fcb,
                          float* __restrict__ out) {
    int row = blockIdx.x;          // t*BB + b
    int t = row >> 5;
    int b = row & 31;
    int c = threadIdx.x >> 5;      // 0..23
    int lane = threadIdx.x & 31;

    const float4* h4 = (const float4*)(g_hout1 + (size_t)row * 1024);
    const float4* w4 = (const float4*)(fcw + (size_t)c * 1024);
    float s = 0.f;
#pragma unroll 4
    for (int k = lane; k < 256; k += 32) {
        float4 a = h4[k], w = w4[k];
        s += a.x * w.x + a.y * w.y + a.z * w.z + a.w * w.w;
    }
#pragma unroll
    for (int o = 16; o; o >>= 1) s += __shfl_xor_sync(0xffffffffu, s, o);
    if (lane == 0) out[((size_t)b * TT + t) * CC + c] = s + fcb[c];
}

// -------------------- CRF per-batch block --------------------
__global__ void crf_block(const float* __restrict__ em, const int* __restrict__ labels,
                          const float* __restrict__ st, const float* __restrict__ en,
                          const float* __restrict__ tr) {
    const int b = blockIdx.x;
    const int cn = threadIdx.x;    // 32 threads, 24 active for DP
    __shared__ float trs[24][25];
    __shared__ float alpha[25];
    __shared__ int   labs[TT];
    __shared__ float s_en[24], s_st[24];

    for (int i = cn; i < 576; i += 32) trs[i / 24][i % 24] = tr[i];
    if (cn < 24) { s_en[cn] = en[cn]; s_st[cn] = st[cn]; }
    for (int i = cn; i < TT; i += 32) labs[i] = labels[b * TT + i];
    __syncwarp();

    const float* emb_ = em + (size_t)b * TT * CC;
    if (cn < 24) alpha[cn] = s_st[cn] + emb_[cn];
    __syncwarp();

    for (int t = 1; t < TT; t++) {
        float anew = 0.f;
        if (cn < 24) {
            float m = -1e30f;
#pragma unroll
            for (int cp = 0; cp < 24; cp++) m = fmaxf(m, alpha[cp] + trs[cp][cn]);
            float s = 0.f;
#pragma unroll
            for (int cp = 0; cp < 24; cp++) s += __expf(alpha[cp] + trs[cp][cn] - m);
            anew = m + __logf(s) + emb_[t * CC + cn];
        }
        __syncwarp();
        if (cn < 24) alpha[cn] = anew;
        __syncwarp();
    }

    float gs = 0.f;
    for (int t = cn; t < TT; t += 32) {
        int tg = labs[t];
        gs += emb_[t * CC + tg];
        if (t > 0) gs += trs[labs[t - 1]][tg];
    }
#pragma unroll
    for (int o = 16; o; o >>= 1) gs += __shfl_xor_sync(0xffffffffu, gs, o);

    if (cn == 0) {
        float m = -1e30f;
        for (int c = 0; c < 24; c++) m = fmaxf(m, alpha[c] + s_en[c]);
        float s = 0.f;
        for (int c = 0; c < 24; c++) s += __expf(alpha[c] + s_en[c] - m);
        float logZ = m + __logf(s);
        float num = gs + s_st[labs[0]] + s_en[labs[TT - 1]];
        g_crf_partial[b] = logZ - num;
    }
}

__global__ void crf_final(float* __restrict__ loss_out) {
    if (threadIdx.x == 0) {
        float L = 0.f;
        for (int b = 0; b < BB; b++) L += g_crf_partial[b];
        loss_out[0] = L;   // -llh
    }
}

// -------------------- launch --------------------
extern "C" void kernel_launch(void* const* d_in, const int* in_sizes, int n_in,
                              void* d_out, int out_size) {
    const int*   x         = (const int*)d_in[0];
    const int*   labels    = (const int*)d_in[1];
    const float* emb       = (const float*)d_in[2];
    const float* w_ih      = (const float*)d_in[3];
    const float* w_hh      = (const float*)d_in[4];
    const float* b_ih      = (const float*)d_in[5];
    const float* b_hh      = (const float*)d_in[6];
    const float* fc_w      = (const float*)d_in[7];
    const float* fc_b      = (const float*)d_in[8];
    const float* crf_start = (const float*)d_in[9];
    const float* crf_end   = (const float*)d_in[10];
    const float* crf_trans = (const float*)d_in[11];
    float* out = (float*)d_out;

    (void)in_sizes; (void)n_in; (void)out_size;

    cudaFuncSetAttribute(lstm_layer_persist,
                         cudaFuncAttributeMaxDynamicSharedMemorySize, L_SMEM_BYTES);
    cudaFuncSetAttribute(gemm_mma,
                         cudaFuncAttributeMaxDynamicSharedMemorySize, GM_SMEM);

    // 1. embedding gather + bf16 split
    gather_split<<<MROWS, 256>>>(x, emb);

    // 2. weight split (both layers)
    wconv<<<8192, 256>>>(w_ih);

    // 3. per-layer: tensor-core input projection, then persistent recurrence
    for (int l = 0; l < 2; l++) {
        const float* whh_l = w_hh + (size_t)l * 2 * NGATE * HH;
        const float* bih_l = b_ih + (size_t)l * NPROJ;
        const float* bhh_l = b_hh + (size_t)l * NPROJ;

        gemm_mma<<<dim3(NPROJ / 128, MROWS / 128), 256, GM_SMEM>>>(l, bih_l, bhh_l);
        zero_state_kernel<<<256, 256>>>();
        lstm_layer_persist<<<128, 128, L_SMEM_BYTES>>>(whh_l, l);
    }

    // 4. FC -> logits into d_out as [b][t][c]
    fc_kernel<<<MROWS, 768>>>(fc_w, fc_b, out);

    // 5. CRF loss -> d_out[B*T*C]
    crf_block<<<BB, 32>>>(out, labels, crf_start, crf_end, crf_trans);
    crf_final<<<1, 32>>>(out + (size_t)BB * TT * CC);
}

// round 13
// speedup vs baseline: 1.4746x; 1.1428x over previous
#include <cuda_runtime.h>
#include <cuda_fp16.h>
#include <cstdint>

typedef unsigned long long u64;

// Problem constants
#define TT 512
#define BB 32
#define EE 1024
#define HH 512
#define CC 24
#define NGATE 2048          // 4*HH
#define NPROJ 4096          // 2 dirs * 4H
#define MROWS (TT*BB)       // 16384

// -------------------- scratch (device globals; no allocation) --------------------
__device__ __half g_x_hi[MROWS * EE];
__device__ __half g_x_lo[MROWS * EE];
__device__ __half g_h0_hi[MROWS * 1024];
__device__ __half g_h0_lo[MROWS * 1024];
__device__ __half g_w_hi[2 * NPROJ * EE];        // fp16-rounded Wih (both layers)
__device__ float g_inproj[MROWS * NPROJ];        // [t][b][dir*2048 + gate*512 + j]
__device__ float g_hout1[MROWS * 1024];          // layer-1 output [t][b][dir*512+j]
__device__ float g_h[2 * 2 * BB * HH];           // [parity][dir][b*H + j]
__device__ unsigned g_bar_cnt[2];
__device__ unsigned g_bar_gen[2];
__device__ float g_crf_partial[BB];

// -------------------- PTX helpers --------------------
__device__ __forceinline__ uint32_t smem_u32(const void* p) {
    uint32_t a;
    asm("{ .reg .u64 t; cvta.to.shared.u64 t, %1; cvt.u32.u64 %0, t; }" : "=r"(a) : "l"(p));
    return a;
}

#define CP_ASYNC16(dst, src) \
    asm volatile("cp.async.cg.shared.global [%0], [%1], 16;" :: "r"(dst), "l"(src) : "memory")
#define CP_COMMIT() asm volatile("cp.async.commit_group;" ::: "memory")
#define CP_WAIT(n)  asm volatile("cp.async.wait_group %0;" :: "n"(n) : "memory")

// mma.sync m16n8k16 row.col fp16 -> f32 accumulate
#define MMA_F16(d, a, b) \
    asm volatile("mma.sync.aligned.m16n8k16.row.col.f32.f16.f16.f32 " \
        "{%0,%1,%2,%3}, {%4,%5,%6,%7}, {%8,%9}, {%0,%1,%2,%3};" \
        : "+f"((d)[0]), "+f"((d)[1]), "+f"((d)[2]), "+f"((d)[3]) \
        : "r"((a)[0]), "r"((a)[1]), "r"((a)[2]), "r"((a)[3]), \
          "r"((b)[0]), "r"((b)[1]))

#define LDSM_X4(r0, r1, r2, r3, addr) \
    asm volatile("ldmatrix.sync.aligned.m8n8.x4.shared.b16 {%0,%1,%2,%3}, [%4];" \
        : "=r"(r0), "=r"(r1), "=r"(r2), "=r"(r3) : "r"(addr))

// packed f32x2 FMA
#define FMA2(acc, x, y) asm("fma.rn.f32x2 %0, %1, %2, %0;" : "+l"(acc) : "l"(x), "l"(y))
__device__ __forceinline__ float sum2(u64 a) {
    float x, y;
    asm("mov.b64 {%0, %1}, %2;" : "=f"(x), "=f"(y) : "l"(a));
    return x + y;
}

__device__ __forceinline__ uint32_t pack_hi2h(float a, float b, float& ra, float& rb) {
    __half ha = __float2half_rn(a), hb = __float2half_rn(b);
    ra = a - __half2float(ha);
    rb = b - __half2float(hb);
    return (uint32_t)__half_as_ushort(ha) | ((uint32_t)__half_as_ushort(hb) << 16);
}
__device__ __forceinline__ uint32_t pack_lo2h(float ra, float rb) {
    __half la = __float2half_rn(ra), lb = __float2half_rn(rb);
    return (uint32_t)__half_as_ushort(la) | ((uint32_t)__half_as_ushort(lb) << 16);
}

// fast, saturating activations (error ~2^-20; no Inf/NaN at extremes)
__device__ __forceinline__ float fast_sigmoid(float x) { return 1.f / (1.f + __expf(-x)); }
__device__ __forceinline__ float fast_tanh(float x)    { return 1.f - 2.f / (1.f + __expf(2.f * x)); }

// -------------------- embedding gather + fp16 split --------------------
__global__ void gather_split(const int* __restrict__ x, const float* __restrict__ emb) {
    int idx = blockIdx.x * blockDim.x + threadIdx.x;   // MROWS * 256
    int e4 = idx & 255;
    int tb = idx >> 8;
    int b = tb & 31, t = tb >> 5;
    int tok = x[b * TT + t];
    float4 v = ((const float4*)(emb + (size_t)tok * EE))[e4];
    float r0, r1, r2, r3;
    uint2 hi, lo;
    hi.x = pack_hi2h(v.x, v.y, r0, r1);
    hi.y = pack_hi2h(v.z, v.w, r2, r3);
    lo.x = pack_lo2h(r0, r1);
    lo.y = pack_lo2h(r2, r3);
    size_t dst = (size_t)tb * EE + e4 * 4;
    *(uint2*)(g_x_hi + dst) = hi;
    *(uint2*)(g_x_lo + dst) = lo;
}

// -------------------- weight convert (fp16 hi only; both layers) --------------------
__global__ void wconv(const float* __restrict__ w_ih) {
    int idx = blockIdx.x * blockDim.x + threadIdx.x;   // 2*4096*1024/4
    float4 v = ((const float4*)w_ih)[idx];
    uint2 hi;
    float r0, r1, r2, r3;
    hi.x = pack_hi2h(v.x, v.y, r0, r1);
    hi.y = pack_hi2h(v.z, v.w, r2, r3);
    *(uint2*)(g_w_hi + (size_t)idx * 4) = hi;
}

// -------------------- tensor-core fp16 2-product GEMM (ldmatrix + 4-stage) ----
// C = A @ W_hi^T + bias, with A = A_hi + A_lo (exact): 2 mma per tile.
#define GP 24                       // smem row pitch in halves (48B)
#define TILE_B (128 * GP * 2)       // 6144 bytes per tensor
#define STAGE_B (3 * TILE_B)        // 18432 bytes per stage (A_hi, A_lo, W_hi)
#define NSTAGE 4
#define GM_SMEM (NSTAGE * STAGE_B)  // 73728

__global__ __launch_bounds__(256, 1)
void gemm_mma(int layer, const float* __restrict__ b1, const float* __restrict__ b2) {
    extern __shared__ char gsm[];
    __shared__ float s_bias[128];

    const int tid = threadIdx.x;
    const int lane = tid & 31, wid = tid >> 5;
    const int wm = wid & 3, wn = wid >> 2;
    const int g = lane >> 2, tq = lane & 3;
    const int m0 = blockIdx.y * 128, n0 = blockIdx.x * 128;

    const __half* A_hi = layer ? g_h0_hi : g_x_hi;
    const __half* A_lo = layer ? g_h0_lo : g_x_lo;
    const __half* srcs[3];
    srcs[0] = A_hi + (size_t)m0 * 1024;
    srcs[1] = A_lo + (size_t)m0 * 1024;
    srcs[2] = g_w_hi + (size_t)layer * NPROJ * EE + (size_t)n0 * 1024;

    if (tid < 128) s_bias[tid] = b1[n0 + tid] + b2[n0 + tid];

    const uint32_t sb = smem_u32(gsm);
    const int row  = tid >> 1;
    const int half = tid & 1;

#define LOAD_STAGE(s, kc) do { \
        uint32_t _d = sb + (s) * STAGE_B + row * 48 + half * 16; \
        size_t _go = (size_t)row * 1024 + (size_t)(kc) * 16 + half * 8; \
        CP_ASYNC16(_d + 0 * TILE_B, srcs[0] + _go); \
        CP_ASYNC16(_d + 1 * TILE_B, srcs[1] + _go); \
        CP_ASYNC16(_d + 2 * TILE_B, srcs[2] + _go); \
        CP_COMMIT(); \
    } while (0)

    uint32_t offA[2], offB[4];
#pragma unroll
    for (int mi = 0; mi < 2; mi++)
        offA[mi] = ((wm * 32 + mi * 16 + (lane & 15)) * GP + (lane >> 4) * 8) * 2;
#pragma unroll
    for (int p = 0; p < 4; p++) {
        int nr = wn * 64 + p * 16;
        offB[p] = ((nr + ((lane >> 4) & 1) * 8 + (lane & 7)) * GP + ((lane >> 3) & 1) * 8) * 2;
    }

    float acc[2][8][4];
#pragma unroll
    for (int mi = 0; mi < 2; mi++)
#pragma unroll
        for (int ni = 0; ni < 8; ni++)
#pragma unroll
            for (int q = 0; q < 4; q++) acc[mi][ni][q] = 0.f;

    LOAD_STAGE(0, 0);
    LOAD_STAGE(1, 1);
    LOAD_STAGE(2, 2);

    for (int kc = 0; kc < 64; kc++) {
        const int s = kc & 3;
        if (kc < 62) CP_WAIT(2);
        else if (kc == 62) CP_WAIT(1);
        else CP_WAIT(0);
        __syncthreads();
        if (kc + 3 < 64) LOAD_STAGE((kc + 3) & 3, kc + 3);

        const uint32_t st = sb + s * STAGE_B;

        uint32_t a_hi[2][4], a_lo[2][4], b_hi[8][2];
#pragma unroll
        for (int mi = 0; mi < 2; mi++) {
            LDSM_X4(a_hi[mi][0], a_hi[mi][1], a_hi[mi][2], a_hi[mi][3], st + 0 * TILE_B + offA[mi]);
            LDSM_X4(a_lo[mi][0], a_lo[mi][1], a_lo[mi][2], a_lo[mi][3], st + 1 * TILE_B + offA[mi]);
        }
#pragma unroll
        for (int p = 0; p < 4; p++) {
            LDSM_X4(b_hi[2 * p][0], b_hi[2 * p][1], b_hi[2 * p + 1][0], b_hi[2 * p + 1][1],
                    st + 2 * TILE_B + offB[p]);
        }

#pragma unroll
        for (int mi = 0; mi < 2; mi++)
#pragma unroll
            for (int ni = 0; ni < 8; ni++) {
                MMA_F16(acc[mi][ni], a_hi[mi], b_hi[ni]);
                MMA_F16(acc[mi][ni], a_lo[mi], b_hi[ni]);
            }
    }

#pragma unroll
    for (int mi = 0; mi < 2; mi++) {
        int mg = m0 + wm * 32 + mi * 16 + g;
#pragma unroll
        for (int ni = 0; ni < 8; ni++) {
            int nl = wn * 64 + ni * 8 + tq * 2;
            int ng = n0 + nl;
            float2 v0, v1;
            v0.x = acc[mi][ni][0] + s_bias[nl];
            v0.y = acc[mi][ni][1] + s_bias[nl + 1];
            v1.x = acc[mi][ni][2] + s_bias[nl];
            v1.y = acc[mi][ni][3] + s_bias[nl + 1];
            *(float2*)(g_inproj + (size_t)mg * NPROJ + ng) = v0;
            *(float2*)(g_inproj + (size_t)(mg + 8) * NPROJ + ng) = v1;
        }
    }
#undef LOAD_STAGE
}

// -------------------- zero h state + reset barriers --------------------
__global__ void zero_state_kernel() {
    int i = blockIdx.x * blockDim.x + threadIdx.x;
    if (i < 2 * 2 * BB * HH) g_h[i] = 0.f;
    if (i < 2) { g_bar_cnt[i] = 0u; g_bar_gen[i] = 0u; }
}

// -------------------- persistent bi-LSTM layer kernel (R8 shape, 256 thr) ------
#define L_SMEM_FLOATS (32*512 + 32*516 + 32*33)
#define L_SMEM_BYTES  (L_SMEM_FLOATS * 4)

__global__ __launch_bounds__(256, 1)
void lstm_layer_persist(const float* __restrict__ whh_l, int layer) {
    extern __shared__ float smem[];
    float* ws  = smem;                          // [row=g*8+jl][512]
    float* hs  = smem + 32 * 512;               // [b][516]
    float* ips = smem + 32 * 512 + 32 * 516;    // [row][33]

    const int dir = (int)blockIdx.x >> 6;
    const int jt  = (int)blockIdx.x & 63;
    const int tid = threadIdx.x;
    const int w   = tid >> 5;
    const int b   = tid & 31;
    const int j   = jt * 8 + w;

    const float* __restrict__ wbase = whh_l + (size_t)dir * 4 * HH * HH;

    for (int i = tid; i < 32 * 128; i += 256) {
        int rw = i >> 7, k4 = i & 127;
        int gg = rw >> 3, jl = rw & 7;
        float4 v = *(const float4*)(wbase + (size_t)(gg * HH + jt * 8 + jl) * HH + k4 * 4);
        *(float4*)(ws + rw * 512 + k4 * 4) = v;
    }
    __syncthreads();

    const int sb  = tid >> 3;
    const int sg  = (tid >> 1) & 3;
    const int sj4 = tid & 1;
    const float* ipg_base = g_inproj + sb * NPROJ + dir * NGATE + sg * HH + jt * 8 + sj4 * 4;

    float c_reg = 0.f;

    for (int t = 0; t < TT; t++) {
        const int p  = t & 1;
        const int tt = dir ? (TT - 1 - t) : t;

        // prefetch step-invariant input projection BEFORE the barrier
        float4 ipv = *(const float4*)(ipg_base + (size_t)tt * 32 * NPROJ);

        if (t > 0) {
            __syncthreads();
            if (tid == 0) {
                __threadfence();
                unsigned a = atomicAdd(&g_bar_cnt[dir], 1u);
                if (a == 63u) {
                    g_bar_cnt[dir] = 0u;
                    __threadfence();
                    atomicExch(&g_bar_gen[dir], (unsigned)t);
                } else {
                    while (*(volatile unsigned*)&g_bar_gen[dir] < (unsigned)t) { }
                }
                __threadfence();
            }
            __syncthreads();
        }

        {
            const float* hsrc = g_h + (size_t)(p * 2 + dir) * (BB * HH);
            for (int i = tid; i < 32 * 128; i += 256) {
                int bb = i >> 7, k4 = i & 127;
                float4 v = *(const float4*)(hsrc + bb * 512 + k4 * 4);
                *(float4*)(hs + bb * 516 + k4 * 4) = v;
            }
        }
        {
            int rbase = sg * 8 + sj4 * 4;
            ips[(rbase + 0) * 33 + sb] = ipv.x;
            ips[(rbase + 1) * 33 + sb] = ipv.y;
            ips[(rbase + 2) * 33 + sb] = ipv.z;
            ips[(rbase + 3) * 33 + sb] = ipv.w;
        }
        __syncthreads();

        const ulonglong2* hp  = (const ulonglong2*)(hs + b * 516);
        const ulonglong2* w0p = (const ulonglong2*)(ws + (0 * 8 + w) * 512);
        const ulonglong2* w1p = (const ulonglong2*)(ws + (1 * 8 + w) * 512);
        const ulonglong2* w2p = (const ulonglong2*)(ws + (2 * 8 + w) * 512);
        const ulonglong2* w3p = (const ulonglong2*)(ws + (3 * 8 + w) * 512);

        u64 ac0 = 0, ac1 = 0, ac2 = 0, ac3 = 0, ac4 = 0, ac5 = 0, ac6 = 0, ac7 = 0;
#pragma unroll 8
        for (int k4 = 0; k4 < 128; k4++) {
            ulonglong2 h2 = hp[k4];
            ulonglong2 q0 = w0p[k4];
            ulonglong2 q1 = w1p[k4];
            ulonglong2 q2 = w2p[k4];
            ulonglong2 q3 = w3p[k4];
            FMA2(ac0, h2.x, q0.x);  FMA2(ac1, h2.y, q0.y);
            FMA2(ac2, h2.x, q1.x);  FMA2(ac3, h2.y, q1.y);
            FMA2(ac4, h2.x, q2.x);  FMA2(ac5, h2.y, q2.y);
            FMA2(ac6, h2.x, q3.x);  FMA2(ac7, h2.y, q3.y);
        }

        float gi = sum2(ac0) + sum2(ac1) + ips[(0 * 8 + w) * 33 + b];
        float gf = sum2(ac2) + sum2(ac3) + ips[(1 * 8 + w) * 33 + b];
        float gg = sum2(ac4) + sum2(ac5) + ips[(2 * 8 + w) * 33 + b];
        float go = sum2(ac6) + sum2(ac7) + ips[(3 * 8 + w) * 33 + b];

        gi = fast_sigmoid(gi);
        gf = fast_sigmoid(gf);
        gg = fast_tanh(gg);
        go = fast_sigmoid(go);

        c_reg = gf * c_reg + gi * gg;
        float h = go * fast_tanh(c_reg);

        g_h[(size_t)((p ^ 1) * 2 + dir) * (BB * HH) + b * 512 + j] = h;

        size_t o = ((size_t)tt * 32 + b) * 1024 + dir * HH + j;
        if (layer == 0) {
            __half hh = __float2half_rn(h);
            __half hl = __float2half_rn(h - __half2float(hh));
            g_h0_hi[o] = hh;
            g_h0_lo[o] = hl;
        } else {
            g_hout1[o] = h;
        }
    }
}

// -------------------- FC: logits[b][t][c] --------------------
__global__ void fc_kernel(const float* __restrict__ fcw, const float* __restrict__ fcb,
                          float* __restrict__ out) {
    int row = blockIdx.x;          // t*BB + b
    int t = row >> 5;
    int b = row & 31;
    int c = threadIdx.x >> 5;      // 0..23
    int lane = threadIdx.x & 31;

    const float4* h4 = (const float4*)(g_hout1 + (size_t)row * 1024);
    const float4* w4 = (const float4*)(fcw + (size_t)c * 1024);
    float s = 0.f;
#pragma unroll 4
    for (int k = lane; k < 256; k += 32) {
        float4 a = h4[k], w = w4[k];
        s += a.x * w.x + a.y * w.y + a.z * w.z + a.w * w.w;
    }
#pragma unroll
    for (int o = 16; o; o >>= 1) s += __shfl_xor_sync(0xffffffffu, s, o);
    if (lane == 0) out[((size_t)b * TT + t) * CC + c] = s + fcb[c];
}

// -------------------- CRF per-batch block --------------------
__global__ void crf_block(const float* __restrict__ em, const int* __restrict__ labels,
                          const float* __restrict__ st, const float* __restrict__ en,
                          const float* __restrict__ tr) {
    const int b = blockIdx.x;
    const int cn = threadIdx.x;    // 32 threads, 24 active for DP
    __shared__ float trs[24][25];
    __shared__ float alpha[25];
    __shared__ int   labs[TT];
    __shared__ float s_en[24], s_st[24];

    for (int i = cn; i < 576; i += 32) trs[i / 24][i % 24] = tr[i];
    if (cn < 24) { s_en[cn] = en[cn]; s_st[cn] = st[cn]; }
    for (int i = cn; i < TT; i += 32) labs[i] = labels[b * TT + i];
    __syncwarp();

    const float* emb_ = em + (size_t)b * TT * CC;
    if (cn < 24) alpha[cn] = s_st[cn] + emb_[cn];
    __syncwarp();

    for (int t = 1; t < TT; t++) {
        float anew = 0.f;
        if (cn < 24) {
            float m = -1e30f;
#pragma unroll
            for (int cp = 0; cp < 24; cp++) m = fmaxf(m, alpha[cp] + trs[cp][cn]);
            float s = 0.f;
#pragma unroll
            for (int cp = 0; cp < 24; cp++) s += __expf(alpha[cp] + trs[cp][cn] - m);
            anew = m + __logf(s) + emb_[t * CC + cn];
        }
        __syncwarp();
        if (cn < 24) alpha[cn] = anew;
        __syncwarp();
    }

    float gs = 0.f;
    for (int t = cn; t < TT; t += 32) {
        int tg = labs[t];
        gs += emb_[t * CC + tg];
        if (t > 0) gs += trs[labs[t - 1]][tg];
    }
#pragma unroll
    for (int o = 16; o; o >>= 1) gs += __shfl_xor_sync(0xffffffffu, gs, o);

    if (cn == 0) {
        float m = -1e30f;
        for (int c = 0; c < 24; c++) m = fmaxf(m, alpha[c] + s_en[c]);
        float s = 0.f;
        for (int c = 0; c < 24; c++) s += __expf(alpha[c] + s_en[c] - m);
        float logZ = m + __logf(s);
        float num = gs + s_st[labs[0]] + s_en[labs[TT - 1]];
        g_crf_partial[b] = logZ - num;
    }
}

__global__ void crf_final(float* __restrict__ loss_out) {
    if (threadIdx.x == 0) {
        float L = 0.f;
        for (int b = 0; b < BB; b++) L += g_crf_partial[b];
        loss_out[0] = L;   // -llh
    }
}

// -------------------- launch --------------------
extern "C" void kernel_launch(void* const* d_in, const int* in_sizes, int n_in,
                              void* d_out, int out_size) {
    const int*   x         = (const int*)d_in[0];
    const int*   labels    = (const int*)d_in[1];
    const float* emb       = (const float*)d_in[2];
    const float* w_ih      = (const float*)d_in[3];
    const float* w_hh      = (const float*)d_in[4];
    const float* b_ih      = (const float*)d_in[5];
    const float* b_hh      = (const float*)d_in[6];
    const float* fc_w      = (const float*)d_in[7];
    const float* fc_b      = (const float*)d_in[8];
    const float* crf_start = (const float*)d_in[9];
    const float* crf_end   = (const float*)d_in[10];
    const float* crf_trans = (const float*)d_in[11];
    float* out = (float*)d_out;

    (void)in_sizes; (void)n_in; (void)out_size;

    cudaFuncSetAttribute(lstm_layer_persist,
                         cudaFuncAttributeMaxDynamicSharedMemorySize, L_SMEM_BYTES);
    cudaFuncSetAttribute(gemm_mma,
                         cudaFuncAttributeMaxDynamicSharedMemorySize, GM_SMEM);

    // 1. embedding gather + fp16 split
    gather_split<<<MROWS, 256>>>(x, emb);

    // 2. weight convert (fp16 hi, both layers)
    wconv<<<8192, 256>>>(w_ih);

    // 3. per-layer: tensor-core input projection, then persistent recurrence
    for (int l = 0; l < 2; l++) {
        const float* whh_l = w_hh + (size_t)l * 2 * NGATE * HH;
        const float* bih_l = b_ih + (size_t)l * NPROJ;
        const float* bhh_l = b_hh + (size_t)l * NPROJ;

        gemm_mma<<<dim3(NPROJ / 128, MROWS / 128), 256, GM_SMEM>>>(l, bih_l, bhh_l);
        zero_state_kernel<<<256, 256>>>();
        lstm_layer_persist<<<128, 256, L_SMEM_BYTES>>>(whh_l, l);
    }

    // 4. FC -> logits into d_out as [b][t][c]
    fc_kernel<<<MROWS, 768>>>(fc_w, fc_b, out);

    // 5. CRF loss -> d_out[B*T*C]
    crf_block<<<BB, 32>>>(out, labels, crf_start, crf_end, crf_trans);
    crf_final<<<1, 32>>>(out + (size_t)BB * TT * CC);
}

// round 14
// speedup vs baseline: 1.5868x; 1.0761x over previous
#include <cuda_runtime.h>
#include <cuda_fp16.h>
#include <cstdint>

typedef unsigned long long u64;

// Problem constants
#define TT 512
#define BB 32
#define EE 1024
#define HH 512
#define CC 24
#define NGATE 2048          // 4*HH
#define NPROJ 4096          // 2 dirs * 4H
#define MROWS (TT*BB)       // 16384

// -------------------- scratch (device globals; no allocation) --------------------
__device__ __half g_x[MROWS * EE];               // fp16 embeddings [t][b][e]
__device__ __half g_h0[MROWS * 1024];            // fp16 layer-0 output
__device__ __half g_w[2 * NPROJ * EE];           // fp16 Wih (both layers)
__device__ float g_inproj[MROWS * NPROJ];        // [t][b][dir*2048 + gate*512 + j]
__device__ float g_hout1[MROWS * 1024];          // layer-1 output [t][b][dir*512+j]
__device__ float g_h[2 * 2 * BB * HH];           // [parity][dir][b*H + j]
__device__ unsigned g_bar_cnt[2];
__device__ unsigned g_bar_gen[2];
__device__ float g_crf_partial[BB];

// -------------------- PTX helpers --------------------
__device__ __forceinline__ uint32_t smem_u32(const void* p) {
    uint32_t a;
    asm("{ .reg .u64 t; cvta.to.shared.u64 t, %1; cvt.u32.u64 %0, t; }" : "=r"(a) : "l"(p));
    return a;
}

#define CP_ASYNC16(dst, src) \
    asm volatile("cp.async.cg.shared.global [%0], [%1], 16;" :: "r"(dst), "l"(src) : "memory")
#define CP_COMMIT() asm volatile("cp.async.commit_group;" ::: "memory")
#define CP_WAIT(n)  asm volatile("cp.async.wait_group %0;" :: "n"(n) : "memory")

// mma.sync m16n8k16 row.col fp16 -> f32 accumulate
#define MMA_F16(d, a, b) \
    asm volatile("mma.sync.aligned.m16n8k16.row.col.f32.f16.f16.f32 " \
        "{%0,%1,%2,%3}, {%4,%5,%6,%7}, {%8,%9}, {%0,%1,%2,%3};" \
        : "+f"((d)[0]), "+f"((d)[1]), "+f"((d)[2]), "+f"((d)[3]) \
        : "r"((a)[0]), "r"((a)[1]), "r"((a)[2]), "r"((a)[3]), \
          "r"((b)[0]), "r"((b)[1]))

#define LDSM_X4(r0, r1, r2, r3, addr) \
    asm volatile("ldmatrix.sync.aligned.m8n8.x4.shared.b16 {%0,%1,%2,%3}, [%4];" \
        : "=r"(r0), "=r"(r1), "=r"(r2), "=r"(r3) : "r"(addr))

// packed f32x2 FMA
#define FMA2(acc, x, y) asm("fma.rn.f32x2 %0, %1, %2, %0;" : "+l"(acc) : "l"(x), "l"(y))
__device__ __forceinline__ float sum2(u64 a) {
    float x, y;
    asm("mov.b64 {%0, %1}, %2;" : "=f"(x), "=f"(y) : "l"(a));
    return x + y;
}

__device__ __forceinline__ uint32_t pack2h(float a, float b) {
    __half ha = __float2half_rn(a), hb = __float2half_rn(b);
    return (uint32_t)__half_as_ushort(ha) | ((uint32_t)__half_as_ushort(hb) << 16);
}

// fast, saturating activations (error ~2^-20; no Inf/NaN at extremes)
__device__ __forceinline__ float fast_sigmoid(float x) { return 1.f / (1.f + __expf(-x)); }
__device__ __forceinline__ float fast_tanh(float x)    { return 1.f - 2.f / (1.f + __expf(2.f * x)); }

// -------------------- embedding gather -> fp16 --------------------
__global__ void gather_split(const int* __restrict__ x, const float* __restrict__ emb) {
    int idx = blockIdx.x * blockDim.x + threadIdx.x;   // MROWS * 256
    int e4 = idx & 255;
    int tb = idx >> 8;
    int b = tb & 31, t = tb >> 5;
    int tok = x[b * TT + t];
    float4 v = ((const float4*)(emb + (size_t)tok * EE))[e4];
    uint2 hv;
    hv.x = pack2h(v.x, v.y);
    hv.y = pack2h(v.z, v.w);
    *(uint2*)(g_x + (size_t)tb * EE + e4 * 4) = hv;
}

// -------------------- weight convert (fp16, both layers) --------------------
__global__ void wconv(const float* __restrict__ w_ih) {
    int idx = blockIdx.x * blockDim.x + threadIdx.x;   // 2*4096*1024/4
    float4 v = ((const float4*)w_ih)[idx];
    uint2 hv;
    hv.x = pack2h(v.x, v.y);
    hv.y = pack2h(v.z, v.w);
    *(uint2*)(g_w + (size_t)idx * 4) = hv;
}

// -------------------- tensor-core pure-fp16 GEMM (ldmatrix + 4-stage) ----
// C = fp16(A) @ fp16(W)^T + bias: 1 mma per tile.
#define GP 24                       // smem row pitch in halves (48B)
#define TILE_B (128 * GP * 2)       // 6144 bytes per tensor
#define STAGE_B (2 * TILE_B)        // 12288 bytes per stage (A, W)
#define NSTAGE 4
#define GM_SMEM (NSTAGE * STAGE_B)  // 49152

__global__ __launch_bounds__(256)
void gemm_mma(int layer, const float* __restrict__ b1, const float* __restrict__ b2) {
    extern __shared__ char gsm[];
    __shared__ float s_bias[128];

    const int tid = threadIdx.x;
    const int lane = tid & 31, wid = tid >> 5;
    const int wm = wid & 3, wn = wid >> 2;
    const int g = lane >> 2, tq = lane & 3;
    const int m0 = blockIdx.y * 128, n0 = blockIdx.x * 128;

    const __half* srcs[2];
    srcs[0] = (layer ? g_h0 : g_x) + (size_t)m0 * 1024;
    srcs[1] = g_w + (size_t)layer * NPROJ * EE + (size_t)n0 * 1024;

    if (tid < 128) s_bias[tid] = b1[n0 + tid] + b2[n0 + tid];

    const uint32_t sb = smem_u32(gsm);
    const int row  = tid >> 1;
    const int half = tid & 1;

#define LOAD_STAGE(s, kc) do { \
        uint32_t _d = sb + (s) * STAGE_B + row * 48 + half * 16; \
        size_t _go = (size_t)row * 1024 + (size_t)(kc) * 16 + half * 8; \
        CP_ASYNC16(_d + 0 * TILE_B, srcs[0] + _go); \
        CP_ASYNC16(_d + 1 * TILE_B, srcs[1] + _go); \
        CP_COMMIT(); \
    } while (0)

    uint32_t offA[2], offB[4];
#pragma unroll
    for (int mi = 0; mi < 2; mi++)
        offA[mi] = ((wm * 32 + mi * 16 + (lane & 15)) * GP + (lane >> 4) * 8) * 2;
#pragma unroll
    for (int p = 0; p < 4; p++) {
        int nr = wn * 64 + p * 16;
        offB[p] = ((nr + ((lane >> 4) & 1) * 8 + (lane & 7)) * GP + ((lane >> 3) & 1) * 8) * 2;
    }

    float acc[2][8][4];
#pragma unroll
    for (int mi = 0; mi < 2; mi++)
#pragma unroll
        for (int ni = 0; ni < 8; ni++)
#pragma unroll
            for (int q = 0; q < 4; q++) acc[mi][ni][q] = 0.f;

    LOAD_STAGE(0, 0);
    LOAD_STAGE(1, 1);
    LOAD_STAGE(2, 2);

    for (int kc = 0; kc < 64; kc++) {
        const int s = kc & 3;
        if (kc < 62) CP_WAIT(2);
        else if (kc == 62) CP_WAIT(1);
        else CP_WAIT(0);
        __syncthreads();
        if (kc + 3 < 64) LOAD_STAGE((kc + 3) & 3, kc + 3);

        const uint32_t st = sb + s * STAGE_B;

        uint32_t a_f[2][4], b_f[8][2];
#pragma unroll
        for (int mi = 0; mi < 2; mi++)
            LDSM_X4(a_f[mi][0], a_f[mi][1], a_f[mi][2], a_f[mi][3], st + 0 * TILE_B + offA[mi]);
#pragma unroll
        for (int p = 0; p < 4; p++)
            LDSM_X4(b_f[2 * p][0], b_f[2 * p][1], b_f[2 * p + 1][0], b_f[2 * p + 1][1],
                    st + 1 * TILE_B + offB[p]);

#pragma unroll
        for (int mi = 0; mi < 2; mi++)
#pragma unroll
            for (int ni = 0; ni < 8; ni++)
                MMA_F16(acc[mi][ni], a_f[mi], b_f[ni]);
    }

#pragma unroll
    for (int mi = 0; mi < 2; mi++) {
        int mg = m0 + wm * 32 + mi * 16 + g;
#pragma unroll
        for (int ni = 0; ni < 8; ni++) {
            int nl = wn * 64 + ni * 8 + tq * 2;
            int ng = n0 + nl;
            float2 v0, v1;
            v0.x = acc[mi][ni][0] + s_bias[nl];
            v0.y = acc[mi][ni][1] + s_bias[nl + 1];
            v1.x = acc[mi][ni][2] + s_bias[nl];
            v1.y = acc[mi][ni][3] + s_bias[nl + 1];
            *(float2*)(g_inproj + (size_t)mg * NPROJ + ng) = v0;
            *(float2*)(g_inproj + (size_t)(mg + 8) * NPROJ + ng) = v1;
        }
    }
#undef LOAD_STAGE
}

// -------------------- zero h state + reset barriers --------------------
__global__ void zero_state_kernel() {
    int i = blockIdx.x * blockDim.x + threadIdx.x;
    if (i < 2 * 2 * BB * HH) g_h[i] = 0.f;
    if (i < 2) { g_bar_cnt[i] = 0u; g_bar_gen[i] = 0u; }
}

// -------------------- persistent bi-LSTM layer kernel (R13 shape) ------
#define L_SMEM_FLOATS (32*512 + 32*516 + 32*33)
#define L_SMEM_BYTES  (L_SMEM_FLOATS * 4)

__global__ __launch_bounds__(256, 1)
void lstm_layer_persist(const float* __restrict__ whh_l, int layer) {
    extern __shared__ float smem[];
    float* ws  = smem;                          // [row=g*8+jl][512]
    float* hs  = smem + 32 * 512;               // [b][516]
    float* ips = smem + 32 * 512 + 32 * 516;    // [row][33]

    const int dir = (int)blockIdx.x >> 6;
    const int jt  = (int)blockIdx.x & 63;
    const int tid = threadIdx.x;
    const int w   = tid >> 5;
    const int b   = tid & 31;
    const int j   = jt * 8 + w;

    const float* __restrict__ wbase = whh_l + (size_t)dir * 4 * HH * HH;

    for (int i = tid; i < 32 * 128; i += 256) {
        int rw = i >> 7, k4 = i & 127;
        int gg = rw >> 3, jl = rw & 7;
        float4 v = *(const float4*)(wbase + (size_t)(gg * HH + jt * 8 + jl) * HH + k4 * 4);
        *(float4*)(ws + rw * 512 + k4 * 4) = v;
    }
    __syncthreads();

    const int sb  = tid >> 3;
    const int sg  = (tid >> 1) & 3;
    const int sj4 = tid & 1;
    const float* ipg_base = g_inproj + sb * NPROJ + dir * NGATE + sg * HH + jt * 8 + sj4 * 4;

    float c_reg = 0.f;

    for (int t = 0; t < TT; t++) {
        const int p  = t & 1;
        const int tt = dir ? (TT - 1 - t) : t;

        // prefetch step-invariant input projection BEFORE the barrier
        float4 ipv = *(const float4*)(ipg_base + (size_t)tt * 32 * NPROJ);

        if (t > 0) {
            __syncthreads();
            if (tid == 0) {
                __threadfence();
                unsigned a = atomicAdd(&g_bar_cnt[dir], 1u);
                if (a == 63u) {
                    g_bar_cnt[dir] = 0u;
                    __threadfence();
                    atomicExch(&g_bar_gen[dir], (unsigned)t);
                } else {
                    while (*(volatile unsigned*)&g_bar_gen[dir] < (unsigned)t) { }
                }
                __threadfence();
            }
            __syncthreads();
        }

        {
            const float* hsrc = g_h + (size_t)(p * 2 + dir) * (BB * HH);
            for (int i = tid; i < 32 * 128; i += 256) {
                int bb = i >> 7, k4 = i & 127;
                float4 v = *(const float4*)(hsrc + bb * 512 + k4 * 4);
                *(float4*)(hs + bb * 516 + k4 * 4) = v;
            }
        }
        {
            int rbase = sg * 8 + sj4 * 4;
            ips[(rbase + 0) * 33 + sb] = ipv.x;
            ips[(rbase + 1) * 33 + sb] = ipv.y;
            ips[(rbase + 2) * 33 + sb] = ipv.z;
            ips[(rbase + 3) * 33 + sb] = ipv.w;
        }
        __syncthreads();

        const ulonglong2* hp  = (const ulonglong2*)(hs + b * 516);
        const ulonglong2* w0p = (const ulonglong2*)(ws + (0 * 8 + w) * 512);
        const ulonglong2* w1p = (const ulonglong2*)(ws + (1 * 8 + w) * 512);
        const ulonglong2* w2p = (const ulonglong2*)(ws + (2 * 8 + w) * 512);
        const ulonglong2* w3p = (const ulonglong2*)(ws + (3 * 8 + w) * 512);

        u64 ac0 = 0, ac1 = 0, ac2 = 0, ac3 = 0, ac4 = 0, ac5 = 0, ac6 = 0, ac7 = 0;
#pragma unroll 8
        for (int k4 = 0; k4 < 128; k4++) {
            ulonglong2 h2 = hp[k4];
            ulonglong2 q0 = w0p[k4];
            ulonglong2 q1 = w1p[k4];
            ulonglong2 q2 = w2p[k4];
            ulonglong2 q3 = w3p[k4];
            FMA2(ac0, h2.x, q0.x);  FMA2(ac1, h2.y, q0.y);
            FMA2(ac2, h2.x, q1.x);  FMA2(ac3, h2.y, q1.y);
            FMA2(ac4, h2.x, q2.x);  FMA2(ac5, h2.y, q2.y);
            FMA2(ac6, h2.x, q3.x);  FMA2(ac7, h2.y, q3.y);
        }

        float gi = sum2(ac0) + sum2(ac1) + ips[(0 * 8 + w) * 33 + b];
        float gf = sum2(ac2) + sum2(ac3) + ips[(1 * 8 + w) * 33 + b];
        float gg = sum2(ac4) + sum2(ac5) + ips[(2 * 8 + w) * 33 + b];
        float go = sum2(ac6) + sum2(ac7) + ips[(3 * 8 + w) * 33 + b];

        gi = fast_sigmoid(gi);
        gf = fast_sigmoid(gf);
        gg = fast_tanh(gg);
        go = fast_sigmoid(go);

        c_reg = gf * c_reg + gi * gg;
        float h = go * fast_tanh(c_reg);

        g_h[(size_t)((p ^ 1) * 2 + dir) * (BB * HH) + b * 512 + j] = h;

        size_t o = ((size_t)tt * 32 + b) * 1024 + dir * HH + j;
        if (layer == 0) {
            g_h0[o] = __float2half_rn(h);
        } else {
            g_hout1[o] = h;
        }
    }
}

// -------------------- FC: logits[b][t][c] --------------------
__global__ void fc_kernel(const float* __restrict__ fcw, const float* __restrict__ fcb,
                          float* __restrict__ out) {
    int row = blockIdx.x;          // t*BB + b
    int t = row >> 5;
    int b = row & 31;
    int c = threadIdx.x >> 5;      // 0..23
    int lane = threadIdx.x & 31;

    const float4* h4 = (const float4*)(g_hout1 + (size_t)row * 1024);
    const float4* w4 = (const float4*)(fcw + (size_t)c * 1024);
    float s = 0.f;
#pragma unroll 4
    for (int k = lane; k < 256; k += 32) {
        float4 a = h4[k], w = w4[k];
        s += a.x * w.x + a.y * w.y + a.z * w.z + a.w * w.w;
    }
#pragma unroll
    for (int o = 16; o; o >>= 1) s += __shfl_xor_sync(0xffffffffu, s, o);
    if (lane == 0) out[((size_t)b * TT + t) * CC + c] = s + fcb[c];
}

// -------------------- CRF per-batch block --------------------
__global__ void crf_block(const float* __restrict__ em, const int* __restrict__ labels,
                          const float* __restrict__ st, const float* __restrict__ en,
                          const float* __restrict__ tr) {
    const int b = blockIdx.x;
    const int cn = threadIdx.x;    // 32 threads, 24 active for DP
    __shared__ float trs[24][25];
    __shared__ float alpha[25];
    __shared__ int   labs[TT];
    __shared__ float s_en[24], s_st[24];

    for (int i = cn; i < 576; i += 32) trs[i / 24][i % 24] = tr[i];
    if (cn < 24) { s_en[cn] = en[cn]; s_st[cn] = st[cn]; }
    for (int i = cn; i < TT; i += 32) labs[i] = labels[b * TT + i];
    __syncwarp();

    const float* emb_ = em + (size_t)b * TT * CC;
    if (cn < 24) alpha[cn] = s_st[cn] + emb_[cn];
    __syncwarp();

    for (int t = 1; t < TT; t++) {
        float anew = 0.f;
        if (cn < 24) {
            float m = -1e30f;
#pragma unroll
            for (int cp = 0; cp < 24; cp++) m = fmaxf(m, alpha[cp] + trs[cp][cn]);
            float s = 0.f;
#pragma unroll
            for (int cp = 0; cp < 24; cp++) s += __expf(alpha[cp] + trs[cp][cn] - m);
            anew = m + __logf(s) + emb_[t * CC + cn];
        }
        __syncwarp();
        if (cn < 24) alpha[cn] = anew;
        __syncwarp();
    }

    float gs = 0.f;
    for (int t = cn; t < TT; t += 32) {
        int tg = labs[t];
        gs += emb_[t * CC + tg];
        if (t > 0) gs += trs[labs[t - 1]][tg];
    }
#pragma unroll
    for (int o = 16; o; o >>= 1) gs += __shfl_xor_sync(0xffffffffu, gs, o);

    if (cn == 0) {
        float m = -1e30f;
        for (int c = 0; c < 24; c++) m = fmaxf(m, alpha[c] + s_en[c]);
        float s = 0.f;
        for (int c = 0; c < 24; c++) s += __expf(alpha[c] + s_en[c] - m);
        float logZ = m + __logf(s);
        float num = gs + s_st[labs[0]] + s_en[labs[TT - 1]];
        g_crf_partial[b] = logZ - num;
    }
}

__global__ void crf_final(float* __restrict__ loss_out) {
    if (threadIdx.x == 0) {
        float L = 0.f;
        for (int b = 0; b < BB; b++) L += g_crf_partial[b];
        loss_out[0] = L;   // -llh
    }
}

// -------------------- launch --------------------
extern "C" void kernel_launch(void* const* d_in, const int* in_sizes, int n_in,
                              void* d_out, int out_size) {
    const int*   x         = (const int*)d_in[0];
    const int*   labels    = (const int*)d_in[1];
    const float* emb       = (const float*)d_in[2];
    const float* w_ih      = (const float*)d_in[3];
    const float* w_hh      = (const float*)d_in[4];
    const float* b_ih      = (const float*)d_in[5];
    const float* b_hh      = (const float*)d_in[6];
    const float* fc_w      = (const float*)d_in[7];
    const float* fc_b      = (const float*)d_in[8];
    const float* crf_start = (const float*)d_in[9];
    const float* crf_end   = (const float*)d_in[10];
    const float* crf_trans = (const float*)d_in[11];
    float* out = (float*)d_out;

    (void)in_sizes; (void)n_in; (void)out_size;

    cudaFuncSetAttribute(lstm_layer_persist,
                         cudaFuncAttributeMaxDynamicSharedMemorySize, L_SMEM_BYTES);
    cudaFuncSetAttribute(gemm_mma,
                         cudaFuncAttributeMaxDynamicSharedMemorySize, GM_SMEM);

    // 1. embedding gather -> fp16
    gather_split<<<MROWS, 256>>>(x, emb);

    // 2. weight convert (fp16, both layers)
    wconv<<<8192, 256>>>(w_ih);

    // 3. per-layer: tensor-core input projection, then persistent recurrence
    for (int l = 0; l < 2; l++) {
        const float* whh_l = w_hh + (size_t)l * 2 * NGATE * HH;
        const float* bih_l = b_ih + (size_t)l * NPROJ;
        const float* bhh_l = b_hh + (size_t)l * NPROJ;

        gemm_mma<<<dim3(NPROJ / 128, MROWS / 128), 256, GM_SMEM>>>(l, bih_l, bhh_l);
        zero_state_kernel<<<256, 256>>>();
        lstm_layer_persist<<<128, 256, L_SMEM_BYTES>>>(whh_l, l);
    }

    // 4. FC -> logits into d_out as [b][t][c]
    fc_kernel<<<MROWS, 768>>>(fc_w, fc_b, out);

    // 5. CRF loss -> d_out[B*T*C]
    crf_block<<<BB, 32>>>(out, labels, crf_start, crf_end, crf_trans);
    crf_final<<<1, 32>>>(out + (size_t)BB * TT * CC);
}

// round 15
// speedup vs baseline: 2.6277x; 1.6559x over previous
#include <cuda_runtime.h>
#include <cuda_fp16.h>
#include <cstdint>

typedef unsigned long long u64;

// Problem constants
#define TT 512
#define BB 32
#define EE 1024
#define HH 512
#define CC 24
#define NGATE 2048          // 4*HH
#define NPROJ 4096          // 2 dirs * 4H
#define MROWS (TT*BB)       // 16384

// -------------------- scratch (device globals; no allocation) --------------------
__device__ __half g_x[MROWS * EE];               // fp16 embeddings [t][b][e]
__device__ __half g_h0[MROWS * 1024];            // fp16 layer-0 output
__device__ __half g_w[2 * NPROJ * EE];           // fp16 Wih (both layers)
__device__ __half g_whh_hi[2 * 2 * NGATE * HH];  // Whh hi, blocked [ld][jt][r=g*8+jl][k]
__device__ __half g_whh_lo[2 * 2 * NGATE * HH];  // Whh lo, same layout
__device__ float g_inproj[MROWS * NPROJ];        // [t][b][dir*2048 + gate*512 + j]
__device__ float g_hout1[MROWS * 1024];          // layer-1 output [t][b][dir*512+j]
__device__ float g_h[2 * 2 * BB * HH];           // [parity][dir][b*H + j]
__device__ unsigned g_bar_cnt[2];
__device__ unsigned g_bar_gen[2];
__device__ float g_crf_partial[BB];

// -------------------- PTX helpers --------------------
__device__ __forceinline__ uint32_t smem_u32(const void* p) {
    uint32_t a;
    asm("{ .reg .u64 t; cvta.to.shared.u64 t, %1; cvt.u32.u64 %0, t; }" : "=r"(a) : "l"(p));
    return a;
}

#define CP_ASYNC16(dst, src) \
    asm volatile("cp.async.cg.shared.global [%0], [%1], 16;" :: "r"(dst), "l"(src) : "memory")
#define CP_COMMIT() asm volatile("cp.async.commit_group;" ::: "memory")
#define CP_WAIT(n)  asm volatile("cp.async.wait_group %0;" :: "n"(n) : "memory")

// mma.sync m16n8k16 row.col fp16 -> f32 accumulate
#define MMA_F16(d, a, b) \
    asm volatile("mma.sync.aligned.m16n8k16.row.col.f32.f16.f16.f32 " \
        "{%0,%1,%2,%3}, {%4,%5,%6,%7}, {%8,%9}, {%0,%1,%2,%3};" \
        : "+f"((d)[0]), "+f"((d)[1]), "+f"((d)[2]), "+f"((d)[3]) \
        : "r"((a)[0]), "r"((a)[1]), "r"((a)[2]), "r"((a)[3]), \
          "r"((b)[0]), "r"((b)[1]))

#define LDSM_X4(r0, r1, r2, r3, addr) \
    asm volatile("ldmatrix.sync.aligned.m8n8.x4.shared.b16 {%0,%1,%2,%3}, [%4];" \
        : "=r"(r0), "=r"(r1), "=r"(r2), "=r"(r3) : "r"(addr))
#define LDSM_X2(r0, r1, addr) \
    asm volatile("ldmatrix.sync.aligned.m8n8.x2.shared.b16 {%0,%1}, [%2];" \
        : "=r"(r0), "=r"(r1) : "r"(addr))

__device__ __forceinline__ uint32_t pack2h(float a, float b) {
    __half ha = __float2half_rn(a), hb = __float2half_rn(b);
    return (uint32_t)__half_as_ushort(ha) | ((uint32_t)__half_as_ushort(hb) << 16);
}
__device__ __forceinline__ uint32_t pack_hi2h(float a, float b, float& ra, float& rb) {
    __half ha = __float2half_rn(a), hb = __float2half_rn(b);
    ra = a - __half2float(ha);
    rb = b - __half2float(hb);
    return (uint32_t)__half_as_ushort(ha) | ((uint32_t)__half_as_ushort(hb) << 16);
}
__device__ __forceinline__ uint32_t pack_lo2h(float ra, float rb) {
    __half la = __float2half_rn(ra), lb = __float2half_rn(rb);
    return (uint32_t)__half_as_ushort(la) | ((uint32_t)__half_as_ushort(lb) << 16);
}

// fast, saturating activations (error ~2^-20; no Inf/NaN at extremes)
__device__ __forceinline__ float fast_sigmoid(float x) { return 1.f / (1.f + __expf(-x)); }
__device__ __forceinline__ float fast_tanh(float x)    { return 1.f - 2.f / (1.f + __expf(2.f * x)); }

// -------------------- embedding gather -> fp16 --------------------
__global__ void gather_split(const int* __restrict__ x, const float* __restrict__ emb) {
    int idx = blockIdx.x * blockDim.x + threadIdx.x;   // MROWS * 256
    int e4 = idx & 255;
    int tb = idx >> 8;
    int b = tb & 31, t = tb >> 5;
    int tok = x[b * TT + t];
    float4 v = ((const float4*)(emb + (size_t)tok * EE))[e4];
    uint2 hv;
    hv.x = pack2h(v.x, v.y);
    hv.y = pack2h(v.z, v.w);
    *(uint2*)(g_x + (size_t)tb * EE + e4 * 4) = hv;
}

// -------------------- Wih convert (fp16, both layers) --------------------
__global__ void wconv(const float* __restrict__ w_ih) {
    int idx = blockIdx.x * blockDim.x + threadIdx.x;   // 2*4096*1024/4
    float4 v = ((const float4*)w_ih)[idx];
    uint2 hv;
    hv.x = pack2h(v.x, v.y);
    hv.y = pack2h(v.z, v.w);
    *(uint2*)(g_w + (size_t)idx * 4) = hv;
}

// -------------------- Whh convert: fp16 hi/lo split, blocked layout ----------
// src row (within [layer][dir]): g*512 + jt*8 + jl ; dst block (ld, jt), row r=g*8+jl
__global__ void wconv_hh(const float* __restrict__ w_hh) {
    int idx = blockIdx.x * blockDim.x + threadIdx.x;   // 2*2*2048*512/4 = 1048576
    int k4 = idx & 127;
    int rowg = idx >> 7;            // 0..16383
    int ld = rowg >> 11;            // layer*2 + dir
    int grow = rowg & 2047;
    int g = grow >> 9;
    int rem = grow & 511;
    int jtt = rem >> 3;
    int jl = rem & 7;
    float4 v = ((const float4*)w_hh)[idx];
    float r0, r1, r2, r3;
    uint2 hi, lo;
    hi.x = pack_hi2h(v.x, v.y, r0, r1);
    hi.y = pack_hi2h(v.z, v.w, r2, r3);
    lo.x = pack_lo2h(r0, r1);
    lo.y = pack_lo2h(r2, r3);
    size_t dst = ((size_t)(ld * 64 + jtt) * 32 + (g * 8 + jl)) * 512 + k4 * 4;
    *(uint2*)(g_whh_hi + dst) = hi;
    *(uint2*)(g_whh_lo + dst) = lo;
}

// -------------------- tensor-core pure-fp16 GEMM (R14, unchanged) ----
#define GP 24                       // smem row pitch in halves (48B)
#define TILE_B (128 * GP * 2)       // 6144 bytes per tensor
#define STAGE_B (2 * TILE_B)        // 12288 bytes per stage (A, W)
#define NSTAGE 4
#define GM_SMEM (NSTAGE * STAGE_B)  // 49152

__global__ __launch_bounds__(256)
void gemm_mma(int layer, const float* __restrict__ b1, const float* __restrict__ b2) {
    extern __shared__ char gsm[];
    __shared__ float s_bias[128];

    const int tid = threadIdx.x;
    const int lane = tid & 31, wid = tid >> 5;
    const int wm = wid & 3, wn = wid >> 2;
    const int g = lane >> 2, tq = lane & 3;
    const int m0 = blockIdx.y * 128, n0 = blockIdx.x * 128;

    const __half* srcs[2];
    srcs[0] = (layer ? g_h0 : g_x) + (size_t)m0 * 1024;
    srcs[1] = g_w + (size_t)layer * NPROJ * EE + (size_t)n0 * 1024;

    if (tid < 128) s_bias[tid] = b1[n0 + tid] + b2[n0 + tid];

    const uint32_t sb = smem_u32(gsm);
    const int row  = tid >> 1;
    const int half = tid & 1;

#define LOAD_STAGE(s, kc) do { \
        uint32_t _d = sb + (s) * STAGE_B + row * 48 + half * 16; \
        size_t _go = (size_t)row * 1024 + (size_t)(kc) * 16 + half * 8; \
        CP_ASYNC16(_d + 0 * TILE_B, srcs[0] + _go); \
        CP_ASYNC16(_d + 1 * TILE_B, srcs[1] + _go); \
        CP_COMMIT(); \
    } while (0)

    uint32_t offA[2], offB[4];
#pragma unroll
    for (int mi = 0; mi < 2; mi++)
        offA[mi] = ((wm * 32 + mi * 16 + (lane & 15)) * GP + (lane >> 4) * 8) * 2;
#pragma unroll
    for (int p = 0; p < 4; p++) {
        int nr = wn * 64 + p * 16;
        offB[p] = ((nr + ((lane >> 4) & 1) * 8 + (lane & 7)) * GP + ((lane >> 3) & 1) * 8) * 2;
    }

    float acc[2][8][4];
#pragma unroll
    for (int mi = 0; mi < 2; mi++)
#pragma unroll
        for (int ni = 0; ni < 8; ni++)
#pragma unroll
            for (int q = 0; q < 4; q++) acc[mi][ni][q] = 0.f;

    LOAD_STAGE(0, 0);
    LOAD_STAGE(1, 1);
    LOAD_STAGE(2, 2);

    for (int kc = 0; kc < 64; kc++) {
        const int s = kc & 3;
        if (kc < 62) CP_WAIT(2);
        else if (kc == 62) CP_WAIT(1);
        else CP_WAIT(0);
        __syncthreads();
        if (kc + 3 < 64) LOAD_STAGE((kc + 3) & 3, kc + 3);

        const uint32_t st = sb + s * STAGE_B;

        uint32_t a_f[2][4], b_f[8][2];
#pragma unroll
        for (int mi = 0; mi < 2; mi++)
            LDSM_X4(a_f[mi][0], a_f[mi][1], a_f[mi][2], a_f[mi][3], st + 0 * TILE_B + offA[mi]);
#pragma unroll
        for (int p = 0; p < 4; p++)
            LDSM_X4(b_f[2 * p][0], b_f[2 * p][1], b_f[2 * p + 1][0], b_f[2 * p + 1][1],
                    st + 1 * TILE_B + offB[p]);

#pragma unroll
        for (int mi = 0; mi < 2; mi++)
#pragma unroll
            for (int ni = 0; ni < 8; ni++)
                MMA_F16(acc[mi][ni], a_f[mi], b_f[ni]);
    }

#pragma unroll
    for (int mi = 0; mi < 2; mi++) {
        int mg = m0 + wm * 32 + mi * 16 + g;
#pragma unroll
        for (int ni = 0; ni < 8; ni++) {
            int nl = wn * 64 + ni * 8 + tq * 2;
            int ng = n0 + nl;
            float2 v0, v1;
            v0.x = acc[mi][ni][0] + s_bias[nl];
            v0.y = acc[mi][ni][1] + s_bias[nl + 1];
            v1.x = acc[mi][ni][2] + s_bias[nl];
            v1.y = acc[mi][ni][3] + s_bias[nl + 1];
            *(float2*)(g_inproj + (size_t)mg * NPROJ + ng) = v0;
            *(float2*)(g_inproj + (size_t)(mg + 8) * NPROJ + ng) = v1;
        }
    }
#undef LOAD_STAGE
}

// -------------------- zero h state + reset barriers --------------------
__global__ void zero_state_kernel() {
    int i = blockIdx.x * blockDim.x + threadIdx.x;
    if (i < 2 * 2 * BB * HH) g_h[i] = 0.f;
    if (i < 2) { g_bar_cnt[i] = 0u; g_bar_gen[i] = 0u; }
}

// -------------------- persistent bi-LSTM layer kernel (tensor-core recurrence) ---
// smem layout (halves pitch 520 for conflict-free ldsm):
#define HP 520
#define OFF_WHI 0
#define OFF_WLO (32 * HP * 2)             // 33280
#define OFF_H   (2 * 32 * HP * 2)         // 66560
#define OFF_C   (3 * 32 * HP * 2)         // 99840 (floats [32 r][33])
#define OFF_IPS (OFF_C + 32 * 33 * 4)     // 104064
#define L2_SMEM (OFF_IPS + 32 * 33 * 4)   // 108288

__global__ __launch_bounds__(256, 1)
void lstm_layer_persist(int layer) {
    extern __shared__ char lsm[];
    const uint32_t sbase = smem_u32(lsm);
    float* Cs  = (float*)(lsm + OFF_C);    // [r][33]
    float* ips = (float*)(lsm + OFF_IPS);  // [row][33]

    const int dir = (int)blockIdx.x >> 6;
    const int jt  = (int)blockIdx.x & 63;
    const int tid = threadIdx.x;
    const int w   = tid >> 5;              // warp 0..7
    const int lane = tid & 31;
    const int b   = lane;                  // for gate combine: lane = batch, w = jl

    // ---- stage Whh hi/lo slice into smem once (pitched) ----
    {
        const uint4* shi = (const uint4*)(g_whh_hi + ((size_t)((layer * 2 + dir) * 64 + jt) * 32) * 512);
        const uint4* slo = (const uint4*)(g_whh_lo + ((size_t)((layer * 2 + dir) * 64 + jt) * 32) * 512);
        for (int i = tid; i < 2048; i += 256) {
            int rw = i >> 6, seg = i & 63;
            uint32_t d = (rw * HP + seg * 8) * 2;
            *(uint4*)(lsm + OFF_WHI + d) = shi[i];
            *(uint4*)(lsm + OFF_WLO + d) = slo[i];
        }
    }
    __syncthreads();

    // mma warp roles: mi = w&1 (16 b), ni = w>>1 (8 r)
    const int mi = w & 1;
    const int ni = w >> 1;
    const uint32_t aoff = sbase + OFF_H +
        (((mi * 16 + (lane & 15)) * HP + (lane >> 4) * 8) * 2);
    const uint32_t bhoff = sbase + OFF_WHI +
        (((ni * 8 + (lane & 7)) * HP + ((lane >> 3) & 1) * 8) * 2);
    const uint32_t bloff = bhoff + (OFF_WLO - OFF_WHI);

    // ip staging map (as R14)
    const int sb2 = tid >> 3;
    const int sg  = (tid >> 1) & 3;
    const int sj4 = tid & 1;
    const float* ipg_base = g_inproj + sb2 * NPROJ + dir * NGATE + sg * HH + jt * 8 + sj4 * 4;

    float c_reg = 0.f;
    const int j = jt * 8 + w;

    for (int t = 0; t < TT; t++) {
        const int p  = t & 1;
        const int tt = dir ? (TT - 1 - t) : t;

        // prefetch step-invariant input projection BEFORE the barrier
        float4 ipv = *(const float4*)(ipg_base + (size_t)tt * 32 * NPROJ);

        if (t > 0) {
            __syncthreads();
            if (tid == 0) {
                __threadfence();
                unsigned a = atomicAdd(&g_bar_cnt[dir], 1u);
                if (a == 63u) {
                    g_bar_cnt[dir] = 0u;
                    __threadfence();
                    atomicExch(&g_bar_gen[dir], (unsigned)t);
                } else {
                    while (*(volatile unsigned*)&g_bar_gen[dir] < (unsigned)t) { }
                }
                __threadfence();
            }
            __syncthreads();
        }

        // ---- stage h(t-1) fp32 -> fp16 smem [b][k], pitch HP ----
        {
            const float* hsrc = g_h + (size_t)(p * 2 + dir) * (BB * HH);
            for (int i = tid; i < 2048; i += 256) {
                int bb = i >> 6, seg = i & 63;
                const float4* s4 = (const float4*)(hsrc + bb * 512 + seg * 8);
                float4 v0 = s4[0], v1 = s4[1];
                uint4 hv;
                hv.x = pack2h(v0.x, v0.y);
                hv.y = pack2h(v0.z, v0.w);
                hv.z = pack2h(v1.x, v1.y);
                hv.w = pack2h(v1.z, v1.w);
                *(uint4*)(lsm + OFF_H + (bb * HP + seg * 8) * 2) = hv;
            }
        }
        // ---- stage input projection ----
        {
            int rbase = sg * 8 + sj4 * 4;
            ips[(rbase + 0) * 33 + sb2] = ipv.x;
            ips[(rbase + 1) * 33 + sb2] = ipv.y;
            ips[(rbase + 2) * 33 + sb2] = ipv.z;
            ips[(rbase + 3) * 33 + sb2] = ipv.w;
        }
        __syncthreads();

        // ---- mma: C[b 16(mi)][r 8(ni)] over K=512, hi+lo products ----
        float ahe[4], aho[4], ale[4], alo4[4];
#pragma unroll
        for (int q = 0; q < 4; q++) { ahe[q] = 0.f; aho[q] = 0.f; ale[q] = 0.f; alo4[q] = 0.f; }

#pragma unroll
        for (int kt = 0; kt < 32; kt += 2) {
            uint32_t a0[4], a1[4], bh0[2], bh1[2], bl0[2], bl1[2];
            LDSM_X4(a0[0], a0[1], a0[2], a0[3], aoff + kt * 32);
            LDSM_X4(a1[0], a1[1], a1[2], a1[3], aoff + kt * 32 + 32);
            LDSM_X2(bh0[0], bh0[1], bhoff + kt * 32);
            LDSM_X2(bh1[0], bh1[1], bhoff + kt * 32 + 32);
            LDSM_X2(bl0[0], bl0[1], bloff + kt * 32);
            LDSM_X2(bl1[0], bl1[1], bloff + kt * 32 + 32);
            MMA_F16(ahe, a0, bh0);
            MMA_F16(aho, a1, bh1);
            MMA_F16(ale, a0, bl0);
            MMA_F16(alo4, a1, bl1);
        }

        // ---- epilogue: acc -> Cs[r][b] ----
        {
            int row0 = mi * 16 + (lane >> 2);       // b
            int col0 = ni * 8 + (lane & 3) * 2;     // r
            float d0 = ahe[0] + aho[0] + ale[0] + alo4[0];
            float d1 = ahe[1] + aho[1] + ale[1] + alo4[1];
            float d2 = ahe[2] + aho[2] + ale[2] + alo4[2];
            float d3 = ahe[3] + aho[3] + ale[3] + alo4[3];
            Cs[col0 * 33 + row0] = d0;
            Cs[(col0 + 1) * 33 + row0] = d1;
            Cs[col0 * 33 + row0 + 8] = d2;
            Cs[(col0 + 1) * 33 + row0 + 8] = d3;
        }
        __syncthreads();

        // ---- gate combine: thread (jl=w, b=lane) ----
        float gi = Cs[(0 * 8 + w) * 33 + b] + ips[(0 * 8 + w) * 33 + b];
        float gf = Cs[(1 * 8 + w) * 33 + b] + ips[(1 * 8 + w) * 33 + b];
        float gg = Cs[(2 * 8 + w) * 33 + b] + ips[(2 * 8 + w) * 33 + b];
        float go = Cs[(3 * 8 + w) * 33 + b] + ips[(3 * 8 + w) * 33 + b];

        gi = fast_sigmoid(gi);
        gf = fast_sigmoid(gf);
        gg = fast_tanh(gg);
        go = fast_sigmoid(go);

        c_reg = gf * c_reg + gi * gg;
        float h = go * fast_tanh(c_reg);

        g_h[(size_t)((p ^ 1) * 2 + dir) * (BB * HH) + b * 512 + j] = h;

        size_t o = ((size_t)tt * 32 + b) * 1024 + dir * HH + j;
        if (layer == 0) {
            g_h0[o] = __float2half_rn(h);
        } else {
            g_hout1[o] = h;
        }
    }
}

// -------------------- FC: logits[b][t][c] --------------------
__global__ void fc_kernel(const float* __restrict__ fcw, const float* __restrict__ fcb,
                          float* __restrict__ out) {
    int row = blockIdx.x;          // t*BB + b
    int t = row >> 5;
    int b = row & 31;
    int c = threadIdx.x >> 5;      // 0..23
    int lane = threadIdx.x & 31;

    const float4* h4 = (const float4*)(g_hout1 + (size_t)row * 1024);
    const float4* w4 = (const float4*)(fcw + (size_t)c * 1024);
    float s = 0.f;
#pragma unroll 4
    for (int k = lane; k < 256; k += 32) {
        float4 a = h4[k], w = w4[k];
        s += a.x * w.x + a.y * w.y + a.z * w.z + a.w * w.w;
    }
#pragma unroll
    for (int o = 16; o; o >>= 1) s += __shfl_xor_sync(0xffffffffu, s, o);
    if (lane == 0) out[((size_t)b * TT + t) * CC + c] = s + fcb[c];
}

// -------------------- CRF per-batch block --------------------
__global__ void crf_block(const float* __restrict__ em, const int* __restrict__ labels,
                          const float* __restrict__ st, const float* __restrict__ en,
                          const float* __restrict__ tr) {
    const int b = blockIdx.x;
    const int cn = threadIdx.x;    // 32 threads, 24 active for DP
    __shared__ float trs[24][25];
    __shared__ float alpha[25];
    __shared__ int   labs[TT];
    __shared__ float s_en[24], s_st[24];

    for (int i = cn; i < 576; i += 32) trs[i / 24][i % 24] = tr[i];
    if (cn < 24) { s_en[cn] = en[cn]; s_st[cn] = st[cn]; }
    for (int i = cn; i < TT; i += 32) labs[i] = labels[b * TT + i];
    __syncwarp();

    const float* emb_ = em + (size_t)b * TT * CC;
    if (cn < 24) alpha[cn] = s_st[cn] + emb_[cn];
    __syncwarp();

    for (int t = 1; t < TT; t++) {
        float anew = 0.f;
        if (cn < 24) {
            float m = -1e30f;
#pragma unroll
            for (int cp = 0; cp < 24; cp++) m = fmaxf(m, alpha[cp] + trs[cp][cn]);
            float s = 0.f;
#pragma unroll
            for (int cp = 0; cp < 24; cp++) s += __expf(alpha[cp] + trs[cp][cn] - m);
            anew = m + __logf(s) + emb_[t * CC + cn];
        }
        __syncwarp();
        if (cn < 24) alpha[cn] = anew;
        __syncwarp();
    }

    float gs = 0.f;
    for (int t = cn; t < TT; t += 32) {
        int tg = labs[t];
        gs += emb_[t * CC + tg];
        if (t > 0) gs += trs[labs[t - 1]][tg];
    }
#pragma unroll
    for (int o = 16; o; o >>= 1) gs += __shfl_xor_sync(0xffffffffu, gs, o);

    if (cn == 0) {
        float m = -1e30f;
        for (int c = 0; c < 24; c++) m = fmaxf(m, alpha[c] + s_en[c]);
        float s = 0.f;
        for (int c = 0; c < 24; c++) s += __expf(alpha[c] + s_en[c] - m);
        float logZ = m + __logf(s);
        float num = gs + s_st[labs[0]] + s_en[labs[TT - 1]];
        g_crf_partial[b] = logZ - num;
    }
}

__global__ void crf_final(float* __restrict__ loss_out) {
    if (threadIdx.x == 0) {
        float L = 0.f;
        for (int b = 0; b < BB; b++) L += g_crf_partial[b];
        loss_out[0] = L;   // -llh
    }
}

// -------------------- launch --------------------
extern "C" void kernel_launch(void* const* d_in, const int* in_sizes, int n_in,
                              void* d_out, int out_size) {
    const int*   x         = (const int*)d_in[0];
    const int*   labels    = (const int*)d_in[1];
    const float* emb       = (const float*)d_in[2];
    const float* w_ih      = (const float*)d_in[3];
    const float* w_hh      = (const float*)d_in[4];
    const float* b_ih      = (const float*)d_in[5];
    const float* b_hh      = (const float*)d_in[6];
    const float* fc_w      = (const float*)d_in[7];
    const float* fc_b      = (const float*)d_in[8];
    const float* crf_start = (const float*)d_in[9];
    const float* crf_end   = (const float*)d_in[10];
    const float* crf_trans = (const float*)d_in[11];
    float* out = (float*)d_out;

    (void)in_sizes; (void)n_in; (void)out_size;

    cudaFuncSetAttribute(lstm_layer_persist,
                         cudaFuncAttributeMaxDynamicSharedMemorySize, L2_SMEM);
    cudaFuncSetAttribute(gemm_mma,
                         cudaFuncAttributeMaxDynamicSharedMemorySize, GM_SMEM);

    // 1. embedding gather -> fp16
    gather_split<<<MROWS, 256>>>(x, emb);

    // 2. weight converts
    wconv<<<8192, 256>>>(w_ih);
    wconv_hh<<<4096, 256>>>(w_hh);

    // 3. per-layer: tensor-core input projection, then tensor-core recurrence
    for (int l = 0; l < 2; l++) {
        const float* bih_l = b_ih + (size_t)l * NPROJ;
        const float* bhh_l = b_hh + (size_t)l * NPROJ;

        gemm_mma<<<dim3(NPROJ / 128, MROWS / 128), 256, GM_SMEM>>>(l, bih_l, bhh_l);
        zero_state_kernel<<<256, 256>>>();
        lstm_layer_persist<<<128, 256, L2_SMEM>>>(l);
    }

    // 4. FC -> logits into d_out as [b][t][c]
    fc_kernel<<<MROWS, 768>>>(fc_w, fc_b, out);

    // 5. CRF loss -> d_out[B*T*C]
    crf_block<<<BB, 32>>>(out, labels, crf_start, crf_end, crf_trans);
    crf_final<<<1, 32>>>(out + (size_t)BB * TT * CC);
}

// round 16
// speedup vs baseline: 2.6298x; 1.0008x over previous
#include <cuda_runtime.h>
#include <cuda_fp16.h>
#include <cstdint>

typedef unsigned long long u64;

// Problem constants
#define TT 512
#define BB 32
#define EE 1024
#define HH 512
#define CC 24
#define NGATE 2048          // 4*HH
#define NPROJ 4096          // 2 dirs * 4H
#define MROWS (TT*BB)       // 16384

// -------------------- scratch (device globals; no allocation) --------------------
__device__ __half g_x[MROWS * EE];               // fp16 embeddings [t][b][e]
__device__ __half g_h0[MROWS * 1024];            // fp16 layer-0 output
__device__ __half g_w[2 * NPROJ * EE];           // fp16 Wih (both layers)
__device__ __half g_whh_hi[2 * 2 * NGATE * HH];  // Whh hi, blocked [ld][jt][r=g*8+jl][k]
__device__ __half g_whh_lo[2 * 2 * NGATE * HH];  // Whh lo, same layout
__device__ float g_inproj[MROWS * NPROJ];        // [t][b][dir*2048 + gate*512 + j]
__device__ float g_hout1[MROWS * 1024];          // layer-1 output [t][b][dir*512+j]
__device__ float g_h[2 * 2 * BB * HH];           // [parity][dir][b*H + j]
__device__ unsigned g_bar_cnt[2];
__device__ unsigned g_bar_gen[2];
__device__ float g_crf_partial[BB];

// -------------------- PTX helpers --------------------
__device__ __forceinline__ uint32_t smem_u32(const void* p) {
    uint32_t a;
    asm("{ .reg .u64 t; cvta.to.shared.u64 t, %1; cvt.u32.u64 %0, t; }" : "=r"(a) : "l"(p));
    return a;
}

#define CP_ASYNC16(dst, src) \
    asm volatile("cp.async.cg.shared.global [%0], [%1], 16;" :: "r"(dst), "l"(src) : "memory")
#define CP_COMMIT() asm volatile("cp.async.commit_group;" ::: "memory")
#define CP_WAIT(n)  asm volatile("cp.async.wait_group %0;" :: "n"(n) : "memory")

// mma.sync m16n8k16 row.col fp16 -> f32 accumulate
#define MMA_F16(d, a, b) \
    asm volatile("mma.sync.aligned.m16n8k16.row.col.f32.f16.f16.f32 " \
        "{%0,%1,%2,%3}, {%4,%5,%6,%7}, {%8,%9}, {%0,%1,%2,%3};" \
        : "+f"((d)[0]), "+f"((d)[1]), "+f"((d)[2]), "+f"((d)[3]) \
        : "r"((a)[0]), "r"((a)[1]), "r"((a)[2]), "r"((a)[3]), \
          "r"((b)[0]), "r"((b)[1]))

#define LDSM_X4(r0, r1, r2, r3, addr) \
    asm volatile("ldmatrix.sync.aligned.m8n8.x4.shared.b16 {%0,%1,%2,%3}, [%4];" \
        : "=r"(r0), "=r"(r1), "=r"(r2), "=r"(r3) : "r"(addr))
#define LDSM_X2(r0, r1, addr) \
    asm volatile("ldmatrix.sync.aligned.m8n8.x2.shared.b16 {%0,%1}, [%2];" \
        : "=r"(r0), "=r"(r1) : "r"(addr))

__device__ __forceinline__ uint32_t pack2h(float a, float b) {
    __half ha = __float2half_rn(a), hb = __float2half_rn(b);
    return (uint32_t)__half_as_ushort(ha) | ((uint32_t)__half_as_ushort(hb) << 16);
}
__device__ __forceinline__ uint32_t pack_hi2h(float a, float b, float& ra, float& rb) {
    __half ha = __float2half_rn(a), hb = __float2half_rn(b);
    ra = a - __half2float(ha);
    rb = b - __half2float(hb);
    return (uint32_t)__half_as_ushort(ha) | ((uint32_t)__half_as_ushort(hb) << 16);
}
__device__ __forceinline__ uint32_t pack_lo2h(float ra, float rb) {
    __half la = __float2half_rn(ra), lb = __float2half_rn(rb);
    return (uint32_t)__half_as_ushort(la) | ((uint32_t)__half_as_ushort(lb) << 16);
}

// fast, saturating activations (error ~2^-20; no Inf/NaN at extremes)
__device__ __forceinline__ float fast_sigmoid(float x) { return 1.f / (1.f + __expf(-x)); }
__device__ __forceinline__ float fast_tanh(float x)    { return 1.f - 2.f / (1.f + __expf(2.f * x)); }

// -------------------- embedding gather -> fp16 --------------------
__global__ void gather_split(const int* __restrict__ x, const float* __restrict__ emb) {
    int idx = blockIdx.x * blockDim.x + threadIdx.x;   // MROWS * 256
    int e4 = idx & 255;
    int tb = idx >> 8;
    int b = tb & 31, t = tb >> 5;
    int tok = x[b * TT + t];
    float4 v = ((const float4*)(emb + (size_t)tok * EE))[e4];
    uint2 hv;
    hv.x = pack2h(v.x, v.y);
    hv.y = pack2h(v.z, v.w);
    *(uint2*)(g_x + (size_t)tb * EE + e4 * 4) = hv;
}

// -------------------- Wih convert (fp16, both layers) --------------------
__global__ void wconv(const float* __restrict__ w_ih) {
    int idx = blockIdx.x * blockDim.x + threadIdx.x;   // 2*4096*1024/4
    float4 v = ((const float4*)w_ih)[idx];
    uint2 hv;
    hv.x = pack2h(v.x, v.y);
    hv.y = pack2h(v.z, v.w);
    *(uint2*)(g_w + (size_t)idx * 4) = hv;
}

// -------------------- Whh convert: fp16 hi/lo split, blocked layout ----------
// src row (within [layer][dir]): g*512 + jt*8 + jl ; dst block (ld, jt), row r=g*8+jl
__global__ void wconv_hh(const float* __restrict__ w_hh) {
    int idx = blockIdx.x * blockDim.x + threadIdx.x;   // 2*2*2048*512/4 = 1048576
    int k4 = idx & 127;
    int rowg = idx >> 7;            // 0..16383
    int ld = rowg >> 11;            // layer*2 + dir
    int grow = rowg & 2047;
    int g = grow >> 9;
    int rem = grow & 511;
    int jtt = rem >> 3;
    int jl = rem & 7;
    float4 v = ((const float4*)w_hh)[idx];
    float r0, r1, r2, r3;
    uint2 hi, lo;
    hi.x = pack_hi2h(v.x, v.y, r0, r1);
    hi.y = pack_hi2h(v.z, v.w, r2, r3);
    lo.x = pack_lo2h(r0, r1);
    lo.y = pack_lo2h(r2, r3);
    size_t dst = ((size_t)(ld * 64 + jtt) * 32 + (g * 8 + jl)) * 512 + k4 * 4;
    *(uint2*)(g_whh_hi + dst) = hi;
    *(uint2*)(g_whh_lo + dst) = lo;
}

// -------------------- tensor-core pure-fp16 GEMM (R14, unchanged) ----
#define GP 24                       // smem row pitch in halves (48B)
#define TILE_B (128 * GP * 2)       // 6144 bytes per tensor
#define STAGE_B (2 * TILE_B)        // 12288 bytes per stage (A, W)
#define NSTAGE 4
#define GM_SMEM (NSTAGE * STAGE_B)  // 49152

__global__ __launch_bounds__(256)
void gemm_mma(int layer, const float* __restrict__ b1, const float* __restrict__ b2) {
    extern __shared__ char gsm[];
    __shared__ float s_bias[128];

    const int tid = threadIdx.x;
    const int lane = tid & 31, wid = tid >> 5;
    const int wm = wid & 3, wn = wid >> 2;
    const int g = lane >> 2, tq = lane & 3;
    const int m0 = blockIdx.y * 128, n0 = blockIdx.x * 128;

    const __half* srcs[2];
    srcs[0] = (layer ? g_h0 : g_x) + (size_t)m0 * 1024;
    srcs[1] = g_w + (size_t)layer * NPROJ * EE + (size_t)n0 * 1024;

    if (tid < 128) s_bias[tid] = b1[n0 + tid] + b2[n0 + tid];

    const uint32_t sb = smem_u32(gsm);
    const int row  = tid >> 1;
    const int half = tid & 1;

#define LOAD_STAGE(s, kc) do { \
        uint32_t _d = sb + (s) * STAGE_B + row * 48 + half * 16; \
        size_t _go = (size_t)row * 1024 + (size_t)(kc) * 16 + half * 8; \
        CP_ASYNC16(_d + 0 * TILE_B, srcs[0] + _go); \
        CP_ASYNC16(_d + 1 * TILE_B, srcs[1] + _go); \
        CP_COMMIT(); \
    } while (0)

    uint32_t offA[2], offB[4];
#pragma unroll
    for (int mi = 0; mi < 2; mi++)
        offA[mi] = ((wm * 32 + mi * 16 + (lane & 15)) * GP + (lane >> 4) * 8) * 2;
#pragma unroll
    for (int p = 0; p < 4; p++) {
        int nr = wn * 64 + p * 16;
        offB[p] = ((nr + ((lane >> 4) & 1) * 8 + (lane & 7)) * GP + ((lane >> 3) & 1) * 8) * 2;
    }

    float acc[2][8][4];
#pragma unroll
    for (int mi = 0; mi < 2; mi++)
#pragma unroll
        for (int ni = 0; ni < 8; ni++)
#pragma unroll
            for (int q = 0; q < 4; q++) acc[mi][ni][q] = 0.f;

    LOAD_STAGE(0, 0);
    LOAD_STAGE(1, 1);
    LOAD_STAGE(2, 2);

    for (int kc = 0; kc < 64; kc++) {
        const int s = kc & 3;
        if (kc < 62) CP_WAIT(2);
        else if (kc == 62) CP_WAIT(1);
        else CP_WAIT(0);
        __syncthreads();
        if (kc + 3 < 64) LOAD_STAGE((kc + 3) & 3, kc + 3);

        const uint32_t st = sb + s * STAGE_B;

        uint32_t a_f[2][4], b_f[8][2];
#pragma unroll
        for (int mi = 0; mi < 2; mi++)
            LDSM_X4(a_f[mi][0], a_f[mi][1], a_f[mi][2], a_f[mi][3], st + 0 * TILE_B + offA[mi]);
#pragma unroll
        for (int p = 0; p < 4; p++)
            LDSM_X4(b_f[2 * p][0], b_f[2 * p][1], b_f[2 * p + 1][0], b_f[2 * p + 1][1],
                    st + 1 * TILE_B + offB[p]);

#pragma unroll
        for (int mi = 0; mi < 2; mi++)
#pragma unroll
            for (int ni = 0; ni < 8; ni++)
                MMA_F16(acc[mi][ni], a_f[mi], b_f[ni]);
    }

#pragma unroll
    for (int mi = 0; mi < 2; mi++) {
        int mg = m0 + wm * 32 + mi * 16 + g;
#pragma unroll
        for (int ni = 0; ni < 8; ni++) {
            int nl = wn * 64 + ni * 8 + tq * 2;
            int ng = n0 + nl;
            float2 v0, v1;
            v0.x = acc[mi][ni][0] + s_bias[nl];
            v0.y = acc[mi][ni][1] + s_bias[nl + 1];
            v1.x = acc[mi][ni][2] + s_bias[nl];
            v1.y = acc[mi][ni][3] + s_bias[nl + 1];
            *(float2*)(g_inproj + (size_t)mg * NPROJ + ng) = v0;
            *(float2*)(g_inproj + (size_t)(mg + 8) * NPROJ + ng) = v1;
        }
    }
#undef LOAD_STAGE
}

// -------------------- zero h state + reset barriers --------------------
__global__ void zero_state_kernel() {
    int i = blockIdx.x * blockDim.x + threadIdx.x;
    if (i < 2 * 2 * BB * HH) g_h[i] = 0.f;
    if (i < 2) { g_bar_cnt[i] = 0u; g_bar_gen[i] = 0u; }
}

// -------------------- persistent bi-LSTM layer kernel (tensor-core recurrence) ---
// smem layout (halves pitch 520 for conflict-free ldsm):
#define HP 520
#define OFF_WHI 0
#define OFF_WLO (32 * HP * 2)             // 33280
#define OFF_H   (2 * 32 * HP * 2)         // 66560
#define OFF_C   (3 * 32 * HP * 2)         // 99840 (floats [32 r][33])
#define OFF_IPS (OFF_C + 32 * 33 * 4)     // 104064
#define L2_SMEM (OFF_IPS + 32 * 33 * 4)   // 108288

__global__ __launch_bounds__(256, 1)
void lstm_layer_persist(int layer) {
    extern __shared__ char lsm[];
    const uint32_t sbase = smem_u32(lsm);
    float* Cs  = (float*)(lsm + OFF_C);    // [r][33]
    float* ips = (float*)(lsm + OFF_IPS);  // [row][33]

    const int dir = (int)blockIdx.x >> 6;
    const int jt  = (int)blockIdx.x & 63;
    const int tid = threadIdx.x;
    const int w   = tid >> 5;              // warp 0..7
    const int lane = tid & 31;
    const int b   = lane;                  // for gate combine: lane = batch, w = jl

    // ---- stage Whh hi/lo slice into smem once (pitched) ----
    {
        const uint4* shi = (const uint4*)(g_whh_hi + ((size_t)((layer * 2 + dir) * 64 + jt) * 32) * 512);
        const uint4* slo = (const uint4*)(g_whh_lo + ((size_t)((layer * 2 + dir) * 64 + jt) * 32) * 512);
        for (int i = tid; i < 2048; i += 256) {
            int rw = i >> 6, seg = i & 63;
            uint32_t d = (rw * HP + seg * 8) * 2;
            *(uint4*)(lsm + OFF_WHI + d) = shi[i];
            *(uint4*)(lsm + OFF_WLO + d) = slo[i];
        }
    }
    __syncthreads();

    // mma warp roles: mi = w&1 (16 b), ni = w>>1 (8 r)
    const int mi = w & 1;
    const int ni = w >> 1;
    const uint32_t aoff = sbase + OFF_H +
        (((mi * 16 + (lane & 15)) * HP + (lane >> 4) * 8) * 2);
    const uint32_t bhoff = sbase + OFF_WHI +
        (((ni * 8 + (lane & 7)) * HP + ((lane >> 3) & 1) * 8) * 2);
    const uint32_t bloff = bhoff + (OFF_WLO - OFF_WHI);

    // ip staging map (as R14)
    const int sb2 = tid >> 3;
    const int sg  = (tid >> 1) & 3;
    const int sj4 = tid & 1;
    const float* ipg_base = g_inproj + sb2 * NPROJ + dir * NGATE + sg * HH + jt * 8 + sj4 * 4;

    float c_reg = 0.f;
    const int j = jt * 8 + w;

    for (int t = 0; t < TT; t++) {
        const int p  = t & 1;
        const int tt = dir ? (TT - 1 - t) : t;

        // prefetch step-invariant input projection BEFORE the barrier
        float4 ipv = *(const float4*)(ipg_base + (size_t)tt * 32 * NPROJ);

        if (t > 0) {
            __syncthreads();
            if (tid == 0) {
                __threadfence();
                unsigned a = atomicAdd(&g_bar_cnt[dir], 1u);
                if (a == 63u) {
                    g_bar_cnt[dir] = 0u;
                    __threadfence();
                    atomicExch(&g_bar_gen[dir], (unsigned)t);
                } else {
                    while (*(volatile unsigned*)&g_bar_gen[dir] < (unsigned)t) { }
                }
                __threadfence();
            }
            __syncthreads();
        }

        // ---- stage h(t-1) fp32 -> fp16 smem [b][k], pitch HP ----
        {
            const float* hsrc = g_h + (size_t)(p * 2 + dir) * (BB * HH);
            for (int i = tid; i < 2048; i += 256) {
                int bb = i >> 6, seg = i & 63;
                const float4* s4 = (const float4*)(hsrc + bb * 512 + seg * 8);
                float4 v0 = s4[0], v1 = s4[1];
                uint4 hv;
                hv.x = pack2h(v0.x, v0.y);
                hv.y = pack2h(v0.z, v0.w);
                hv.z = pack2h(v1.x, v1.y);
                hv.w = pack2h(v1.z, v1.w);
                *(uint4*)(lsm + OFF_H + (bb * HP + seg * 8) * 2) = hv;
            }
        }
        // ---- stage input projection ----
        {
            int rbase = sg * 8 + sj4 * 4;
            ips[(rbase + 0) * 33 + sb2] = ipv.x;
            ips[(rbase + 1) * 33 + sb2] = ipv.y;
            ips[(rbase + 2) * 33 + sb2] = ipv.z;
            ips[(rbase + 3) * 33 + sb2] = ipv.w;
        }
        __syncthreads();

        // ---- mma: C[b 16(mi)][r 8(ni)] over K=512, hi+lo products ----
        float ahe[4], aho[4], ale[4], alo4[4];
#pragma unroll
        for (int q = 0; q < 4; q++) { ahe[q] = 0.f; aho[q] = 0.f; ale[q] = 0.f; alo4[q] = 0.f; }

#pragma unroll
        for (int kt = 0; kt < 32; kt += 2) {
            uint32_t a0[4], a1[4], bh0[2], bh1[2], bl0[2], bl1[2];
            LDSM_X4(a0[0], a0[1], a0[2], a0[3], aoff + kt * 32);
            LDSM_X4(a1[0], a1[1], a1[2], a1[3], aoff + kt * 32 + 32);
            LDSM_X2(bh0[0], bh0[1], bhoff + kt * 32);
            LDSM_X2(bh1[0], bh1[1], bhoff + kt * 32 + 32);
            LDSM_X2(bl0[0], bl0[1], bloff + kt * 32);
            LDSM_X2(bl1[0], bl1[1], bloff + kt * 32 + 32);
            MMA_F16(ahe, a0, bh0);
            MMA_F16(aho, a1, bh1);
            MMA_F16(ale, a0, bl0);
            MMA_F16(alo4, a1, bl1);
        }

        // ---- epilogue: acc -> Cs[r][b] ----
        {
            int row0 = mi * 16 + (lane >> 2);       // b
            int col0 = ni * 8 + (lane & 3) * 2;     // r
            float d0 = ahe[0] + aho[0] + ale[0] + alo4[0];
            float d1 = ahe[1] + aho[1] + ale[1] + alo4[1];
            float d2 = ahe[2] + aho[2] + ale[2] + alo4[2];
            float d3 = ahe[3] + aho[3] + ale[3] + alo4[3];
            Cs[col0 * 33 + row0] = d0;
            Cs[(col0 + 1) * 33 + row0] = d1;
            Cs[col0 * 33 + row0 + 8] = d2;
            Cs[(col0 + 1) * 33 + row0 + 8] = d3;
        }
        __syncthreads();

        // ---- gate combine: thread (jl=w, b=lane) ----
        float gi = Cs[(0 * 8 + w) * 33 + b] + ips[(0 * 8 + w) * 33 + b];
        float gf = Cs[(1 * 8 + w) * 33 + b] + ips[(1 * 8 + w) * 33 + b];
        float gg = Cs[(2 * 8 + w) * 33 + b] + ips[(2 * 8 + w) * 33 + b];
        float go = Cs[(3 * 8 + w) * 33 + b] + ips[(3 * 8 + w) * 33 + b];

        gi = fast_sigmoid(gi);
        gf = fast_sigmoid(gf);
        gg = fast_tanh(gg);
        go = fast_sigmoid(go);

        c_reg = gf * c_reg + gi * gg;
        float h = go * fast_tanh(c_reg);

        g_h[(size_t)((p ^ 1) * 2 + dir) * (BB * HH) + b * 512 + j] = h;

        size_t o = ((size_t)tt * 32 + b) * 1024 + dir * HH + j;
        if (layer == 0) {
            g_h0[o] = __float2half_rn(h);
        } else {
            g_hout1[o] = h;
        }
    }
}

// -------------------- FC: logits[b][t][c] --------------------
__global__ void fc_kernel(const float* __restrict__ fcw, const float* __restrict__ fcb,
                          float* __restrict__ out) {
    int row = blockIdx.x;          // t*BB + b
    int t = row >> 5;
    int b = row & 31;
    int c = threadIdx.x >> 5;      // 0..23
    int lane = threadIdx.x & 31;

    const float4* h4 = (const float4*)(g_hout1 + (size_t)row * 1024);
    const float4* w4 = (const float4*)(fcw + (size_t)c * 1024);
    float s = 0.f;
#pragma unroll 4
    for (int k = lane; k < 256; k += 32) {
        float4 a = h4[k], w = w4[k];
        s += a.x * w.x + a.y * w.y + a.z * w.z + a.w * w.w;
    }
#pragma unroll
    for (int o = 16; o; o >>= 1) s += __shfl_xor_sync(0xffffffffu, s, o);
    if (lane == 0) out[((size_t)b * TT + t) * CC + c] = s + fcb[c];
}

// -------------------- CRF per-batch block --------------------
__global__ void crf_block(const float* __restrict__ em, const int* __restrict__ labels,
                          const float* __restrict__ st, const float* __restrict__ en,
                          const float* __restrict__ tr) {
    const int b = blockIdx.x;
    const int cn = threadIdx.x;    // 32 threads, 24 active for DP
    __shared__ float trs[24][25];
    __shared__ float alpha[25];
    __shared__ int   labs[TT];
    __shared__ float s_en[24], s_st[24];

    for (int i = cn; i < 576; i += 32) trs[i / 24][i % 24] = tr[i];
    if (cn < 24) { s_en[cn] = en[cn]; s_st[cn] = st[cn]; }
    for (int i = cn; i < TT; i += 32) labs[i] = labels[b * TT + i];
    __syncwarp();

    const float* emb_ = em + (size_t)b * TT * CC;
    if (cn < 24) alpha[cn] = s_st[cn] + emb_[cn];
    __syncwarp();

    for (int t = 1; t < TT; t++) {
        float anew = 0.f;
        if (cn < 24) {
            float m = -1e30f;
#pragma unroll
            for (int cp = 0; cp < 24; cp++) m = fmaxf(m, alpha[cp] + trs[cp][cn]);
            float s = 0.f;
#pragma unroll
            for (int cp = 0; cp < 24; cp++) s += __expf(alpha[cp] + trs[cp][cn] - m);
            anew = m + __logf(s) + emb_[t * CC + cn];
        }
        __syncwarp();
        if (cn < 24) alpha[cn] = anew;
        __syncwarp();
    }

    float gs = 0.f;
    for (int t = cn; t < TT; t += 32) {
        int tg = labs[t];
        gs += emb_[t * CC + tg];
        if (t > 0) gs += trs[labs[t - 1]][tg];
    }
#pragma unroll
    for (int o = 16; o; o >>= 1) gs += __shfl_xor_sync(0xffffffffu, gs, o);

    if (cn == 0) {
        float m = -1e30f;
        for (int c = 0; c < 24; c++) m = fmaxf(m, alpha[c] + s_en[c]);
        float s = 0.f;
        for (int c = 0; c < 24; c++) s += __expf(alpha[c] + s_en[c] - m);
        float logZ = m + __logf(s);
        float num = gs + s_st[labs[0]] + s_en[labs[TT - 1]];
        g_crf_partial[b] = logZ - num;
    }
}

__global__ void crf_final(float* __restrict__ loss_out) {
    if (threadIdx.x == 0) {
        float L = 0.f;
        for (int b = 0; b < BB; b++) L += g_crf_partial[b];
        loss_out[0] = L;   // -llh
    }
}

// -------------------- launch --------------------
extern "C" void kernel_launch(void* const* d_in, const int* in_sizes, int n_in,
                              void* d_out, int out_size) {
    const int*   x         = (const int*)d_in[0];
    const int*   labels    = (const int*)d_in[1];
    const float* emb       = (const float*)d_in[2];
    const float* w_ih      = (const float*)d_in[3];
    const float* w_hh      = (const float*)d_in[4];
    const float* b_ih      = (const float*)d_in[5];
    const float* b_hh      = (const float*)d_in[6];
    const float* fc_w      = (const float*)d_in[7];
    const float* fc_b      = (const float*)d_in[8];
    const float* crf_start = (const float*)d_in[9];
    const float* crf_end   = (const float*)d_in[10];
    const float* crf_trans = (const float*)d_in[11];
    float* out = (float*)d_out;

    (void)in_sizes; (void)n_in; (void)out_size;

    cudaFuncSetAttribute(lstm_layer_persist,
                         cudaFuncAttributeMaxDynamicSharedMemorySize, L2_SMEM);
    cudaFuncSetAttribute(gemm_mma,
                         cudaFuncAttributeMaxDynamicSharedMemorySize, GM_SMEM);

    // 1. embedding gather -> fp16
    gather_split<<<MROWS, 256>>>(x, emb);

    // 2. weight converts
    wconv<<<8192, 256>>>(w_ih);
    wconv_hh<<<4096, 256>>>(w_hh);

    // 3. per-layer: tensor-core input projection, then tensor-core recurrence
    for (int l = 0; l < 2; l++) {
        const float* bih_l = b_ih + (size_t)l * NPROJ;
        const float* bhh_l = b_hh + (size_t)l * NPROJ;

        gemm_mma<<<dim3(NPROJ / 128, MROWS / 128), 256, GM_SMEM>>>(l, bih_l, bhh_l);
        zero_state_kernel<<<256, 256>>>();
        lstm_layer_persist<<<128, 256, L2_SMEM>>>(l);
    }

    // 4. FC -> logits into d_out as [b][t][c]
    fc_kernel<<<MROWS, 768>>>(fc_w, fc_b, out);

    // 5. CRF loss -> d_out[B*T*C]
    crf_block<<<BB, 32>>>(out, labels, crf_start, crf_end, crf_trans);
    crf_final<<<1, 32>>>(out + (size_t)BB * TT * CC);
}

// round 17
// speedup vs baseline: 2.6308x; 1.0004x over previous
#include <cuda_runtime.h>
#include <cuda_fp16.h>
#include <cstdint>

typedef unsigned long long u64;

// Problem constants
#define TT 512
#define BB 32
#define EE 1024
#define HH 512
#define CC 24
#define NGATE 2048          // 4*HH
#define NPROJ 4096          // 2 dirs * 4H
#define MROWS (TT*BB)       // 16384

// -------------------- scratch (device globals; no allocation) --------------------
__device__ __half g_x[MROWS * EE];               // fp16 embeddings [t][b][e]
__device__ __half g_h0[MROWS * 1024];            // fp16 layer-0 output
__device__ __half g_w[2 * NPROJ * EE];           // fp16 Wih (both layers)
__device__ __half g_whh_hi[2 * 2 * NGATE * HH];  // Whh hi, blocked [ld][jt][r=g*8+jl][k]
__device__ __half g_whh_lo[2 * 2 * NGATE * HH];  // Whh lo, same layout
__device__ float g_inproj[MROWS * NPROJ];        // [t][b][dir*2048 + gate*512 + j]
__device__ float g_hout1[MROWS * 1024];          // layer-1 output [t][b][dir*512+j]
__device__ float g_h[2 * 2 * BB * HH];           // [parity][dir][b*H + j]
__device__ unsigned g_bar_cnt[2];
__device__ unsigned g_bar_gen[2];
__device__ float g_crf_partial[BB];

// -------------------- PTX helpers --------------------
__device__ __forceinline__ uint32_t smem_u32(const void* p) {
    uint32_t a;
    asm("{ .reg .u64 t; cvta.to.shared.u64 t, %1; cvt.u32.u64 %0, t; }" : "=r"(a) : "l"(p));
    return a;
}

#define CP_ASYNC16(dst, src) \
    asm volatile("cp.async.cg.shared.global [%0], [%1], 16;" :: "r"(dst), "l"(src) : "memory")
#define CP_COMMIT() asm volatile("cp.async.commit_group;" ::: "memory")
#define CP_WAIT(n)  asm volatile("cp.async.wait_group %0;" :: "n"(n) : "memory")

// mma.sync m16n8k16 row.col fp16 -> f32 accumulate
#define MMA_F16(d, a, b) \
    asm volatile("mma.sync.aligned.m16n8k16.row.col.f32.f16.f16.f32 " \
        "{%0,%1,%2,%3}, {%4,%5,%6,%7}, {%8,%9}, {%0,%1,%2,%3};" \
        : "+f"((d)[0]), "+f"((d)[1]), "+f"((d)[2]), "+f"((d)[3]) \
        : "r"((a)[0]), "r"((a)[1]), "r"((a)[2]), "r"((a)[3]), \
          "r"((b)[0]), "r"((b)[1]))

#define LDSM_X4(r0, r1, r2, r3, addr) \
    asm volatile("ldmatrix.sync.aligned.m8n8.x4.shared.b16 {%0,%1,%2,%3}, [%4];" \
        : "=r"(r0), "=r"(r1), "=r"(r2), "=r"(r3) : "r"(addr))
#define LDSM_X2(r0, r1, addr) \
    asm volatile("ldmatrix.sync.aligned.m8n8.x2.shared.b16 {%0,%1}, [%2];" \
        : "=r"(r0), "=r"(r1) : "r"(addr))

__device__ __forceinline__ uint32_t pack2h(float a, float b) {
    __half ha = __float2half_rn(a), hb = __float2half_rn(b);
    return (uint32_t)__half_as_ushort(ha) | ((uint32_t)__half_as_ushort(hb) << 16);
}
__device__ __forceinline__ uint32_t pack_hi2h(float a, float b, float& ra, float& rb) {
    __half ha = __float2half_rn(a), hb = __float2half_rn(b);
    ra = a - __half2float(ha);
    rb = b - __half2float(hb);
    return (uint32_t)__half_as_ushort(ha) | ((uint32_t)__half_as_ushort(hb) << 16);
}
__device__ __forceinline__ uint32_t pack_lo2h(float ra, float rb) {
    __half la = __float2half_rn(ra), lb = __float2half_rn(rb);
    return (uint32_t)__half_as_ushort(la) | ((uint32_t)__half_as_ushort(lb) << 16);
}

// fast, saturating activations (error ~2^-20; no Inf/NaN at extremes)
__device__ __forceinline__ float fast_sigmoid(float x) { return 1.f / (1.f + __expf(-x)); }
__device__ __forceinline__ float fast_tanh(float x)    { return 1.f - 2.f / (1.f + __expf(2.f * x)); }

// -------------------- embedding gather -> fp16 --------------------
__global__ void gather_split(const int* __restrict__ x, const float* __restrict__ emb) {
    int idx = blockIdx.x * blockDim.x + threadIdx.x;   // MROWS * 256
    int e4 = idx & 255;
    int tb = idx >> 8;
    int b = tb & 31, t = tb >> 5;
    int tok = x[b * TT + t];
    float4 v = ((const float4*)(emb + (size_t)tok * EE))[e4];
    uint2 hv;
    hv.x = pack2h(v.x, v.y);
    hv.y = pack2h(v.z, v.w);
    *(uint2*)(g_x + (size_t)tb * EE + e4 * 4) = hv;
}

// -------------------- Wih convert (fp16, both layers) --------------------
__global__ void wconv(const float* __restrict__ w_ih) {
    int idx = blockIdx.x * blockDim.x + threadIdx.x;   // 2*4096*1024/4
    float4 v = ((const float4*)w_ih)[idx];
    uint2 hv;
    hv.x = pack2h(v.x, v.y);
    hv.y = pack2h(v.z, v.w);
    *(uint2*)(g_w + (size_t)idx * 4) = hv;
}

// -------------------- Whh convert: fp16 hi/lo split, blocked layout ----------
// src row (within [layer][dir]): g*512 + jt*8 + jl ; dst block (ld, jt), row r=g*8+jl
__global__ void wconv_hh(const float* __restrict__ w_hh) {
    int idx = blockIdx.x * blockDim.x + threadIdx.x;   // 2*2*2048*512/4 = 1048576
    int k4 = idx & 127;
    int rowg = idx >> 7;            // 0..16383
    int ld = rowg >> 11;            // layer*2 + dir
    int grow = rowg & 2047;
    int g = grow >> 9;
    int rem = grow & 511;
    int jtt = rem >> 3;
    int jl = rem & 7;
    float4 v = ((const float4*)w_hh)[idx];
    float r0, r1, r2, r3;
    uint2 hi, lo;
    hi.x = pack_hi2h(v.x, v.y, r0, r1);
    hi.y = pack_hi2h(v.z, v.w, r2, r3);
    lo.x = pack_lo2h(r0, r1);
    lo.y = pack_lo2h(r2, r3);
    size_t dst = ((size_t)(ld * 64 + jtt) * 32 + (g * 8 + jl)) * 512 + k4 * 4;
    *(uint2*)(g_whh_hi + dst) = hi;
    *(uint2*)(g_whh_lo + dst) = lo;
}

// -------------------- tensor-core pure-fp16 GEMM (R14, unchanged) ----
#define GP 24                       // smem row pitch in halves (48B)
#define TILE_B (128 * GP * 2)       // 6144 bytes per tensor
#define STAGE_B (2 * TILE_B)        // 12288 bytes per stage (A, W)
#define NSTAGE 4
#define GM_SMEM (NSTAGE * STAGE_B)  // 49152

__global__ __launch_bounds__(256)
void gemm_mma(int layer, const float* __restrict__ b1, const float* __restrict__ b2) {
    extern __shared__ char gsm[];
    __shared__ float s_bias[128];

    const int tid = threadIdx.x;
    const int lane = tid & 31, wid = tid >> 5;
    const int wm = wid & 3, wn = wid >> 2;
    const int g = lane >> 2, tq = lane & 3;
    const int m0 = blockIdx.y * 128, n0 = blockIdx.x * 128;

    const __half* srcs[2];
    srcs[0] = (layer ? g_h0 : g_x) + (size_t)m0 * 1024;
    srcs[1] = g_w + (size_t)layer * NPROJ * EE + (size_t)n0 * 1024;

    if (tid < 128) s_bias[tid] = b1[n0 + tid] + b2[n0 + tid];

    const uint32_t sb = smem_u32(gsm);
    const int row  = tid >> 1;
    const int half = tid & 1;

#define LOAD_STAGE(s, kc) do { \
        uint32_t _d = sb + (s) * STAGE_B + row * 48 + half * 16; \
        size_t _go = (size_t)row * 1024 + (size_t)(kc) * 16 + half * 8; \
        CP_ASYNC16(_d + 0 * TILE_B, srcs[0] + _go); \
        CP_ASYNC16(_d + 1 * TILE_B, srcs[1] + _go); \
        CP_COMMIT(); \
    } while (0)

    uint32_t offA[2], offB[4];
#pragma unroll
    for (int mi = 0; mi < 2; mi++)
        offA[mi] = ((wm * 32 + mi * 16 + (lane & 15)) * GP + (lane >> 4) * 8) * 2;
#pragma unroll
    for (int p = 0; p < 4; p++) {
        int nr = wn * 64 + p * 16;
        offB[p] = ((nr + ((lane >> 4) & 1) * 8 + (lane & 7)) * GP + ((lane >> 3) & 1) * 8) * 2;
    }

    float acc[2][8][4];
#pragma unroll
    for (int mi = 0; mi < 2; mi++)
#pragma unroll
        for (int ni = 0; ni < 8; ni++)
#pragma unroll
            for (int q = 0; q < 4; q++) acc[mi][ni][q] = 0.f;

    LOAD_STAGE(0, 0);
    LOAD_STAGE(1, 1);
    LOAD_STAGE(2, 2);

    for (int kc = 0; kc < 64; kc++) {
        const int s = kc & 3;
        if (kc < 62) CP_WAIT(2);
        else if (kc == 62) CP_WAIT(1);
        else CP_WAIT(0);
        __syncthreads();
        if (kc + 3 < 64) LOAD_STAGE((kc + 3) & 3, kc + 3);

        const uint32_t st = sb + s * STAGE_B;

        uint32_t a_f[2][4], b_f[8][2];
#pragma unroll
        for (int mi = 0; mi < 2; mi++)
            LDSM_X4(a_f[mi][0], a_f[mi][1], a_f[mi][2], a_f[mi][3], st + 0 * TILE_B + offA[mi]);
#pragma unroll
        for (int p = 0; p < 4; p++)
            LDSM_X4(b_f[2 * p][0], b_f[2 * p][1], b_f[2 * p + 1][0], b_f[2 * p + 1][1],
                    st + 1 * TILE_B + offB[p]);

#pragma unroll
        for (int mi = 0; mi < 2; mi++)
#pragma unroll
            for (int ni = 0; ni < 8; ni++)
                MMA_F16(acc[mi][ni], a_f[mi], b_f[ni]);
    }

#pragma unroll
    for (int mi = 0; mi < 2; mi++) {
        int mg = m0 + wm * 32 + mi * 16 + g;
#pragma unroll
        for (int ni = 0; ni < 8; ni++) {
            int nl = wn * 64 + ni * 8 + tq * 2;
            int ng = n0 + nl;
            float2 v0, v1;
            v0.x = acc[mi][ni][0] + s_bias[nl];
            v0.y = acc[mi][ni][1] + s_bias[nl + 1];
            v1.x = acc[mi][ni][2] + s_bias[nl];
            v1.y = acc[mi][ni][3] + s_bias[nl + 1];
            *(float2*)(g_inproj + (size_t)mg * NPROJ + ng) = v0;
            *(float2*)(g_inproj + (size_t)(mg + 8) * NPROJ + ng) = v1;
        }
    }
#undef LOAD_STAGE
}

// -------------------- zero h state + reset barriers --------------------
__global__ void zero_state_kernel() {
    int i = blockIdx.x * blockDim.x + threadIdx.x;
    if (i < 2 * 2 * BB * HH) g_h[i] = 0.f;
    if (i < 2) { g_bar_cnt[i] = 0u; g_bar_gen[i] = 0u; }
}

// -------------------- persistent bi-LSTM layer kernel (tensor-core recurrence) ---
// smem layout (halves pitch 520 for conflict-free ldsm):
#define HP 520
#define OFF_WHI 0
#define OFF_WLO (32 * HP * 2)             // 33280
#define OFF_H   (2 * 32 * HP * 2)         // 66560
#define OFF_C   (3 * 32 * HP * 2)         // 99840 (floats [32 r][33])
#define OFF_IPS (OFF_C + 32 * 33 * 4)     // 104064
#define L2_SMEM (OFF_IPS + 32 * 33 * 4)   // 108288

__global__ __launch_bounds__(256, 1)
void lstm_layer_persist(int layer) {
    extern __shared__ char lsm[];
    const uint32_t sbase = smem_u32(lsm);
    float* Cs  = (float*)(lsm + OFF_C);    // [r][33]
    float* ips = (float*)(lsm + OFF_IPS);  // [row][33]

    const int dir = (int)blockIdx.x >> 6;
    const int jt  = (int)blockIdx.x & 63;
    const int tid = threadIdx.x;
    const int w   = tid >> 5;              // warp 0..7
    const int lane = tid & 31;
    const int b   = lane;                  // for gate combine: lane = batch, w = jl

    // ---- stage Whh hi/lo slice into smem once (pitched) ----
    {
        const uint4* shi = (const uint4*)(g_whh_hi + ((size_t)((layer * 2 + dir) * 64 + jt) * 32) * 512);
        const uint4* slo = (const uint4*)(g_whh_lo + ((size_t)((layer * 2 + dir) * 64 + jt) * 32) * 512);
        for (int i = tid; i < 2048; i += 256) {
            int rw = i >> 6, seg = i & 63;
            uint32_t d = (rw * HP + seg * 8) * 2;
            *(uint4*)(lsm + OFF_WHI + d) = shi[i];
            *(uint4*)(lsm + OFF_WLO + d) = slo[i];
        }
    }
    __syncthreads();

    // mma warp roles: mi = w&1 (16 b), ni = w>>1 (8 r)
    const int mi = w & 1;
    const int ni = w >> 1;
    const uint32_t aoff = sbase + OFF_H +
        (((mi * 16 + (lane & 15)) * HP + (lane >> 4) * 8) * 2);
    const uint32_t bhoff = sbase + OFF_WHI +
        (((ni * 8 + (lane & 7)) * HP + ((lane >> 3) & 1) * 8) * 2);
    const uint32_t bloff = bhoff + (OFF_WLO - OFF_WHI);

    // ip staging map (as R14)
    const int sb2 = tid >> 3;
    const int sg  = (tid >> 1) & 3;
    const int sj4 = tid & 1;
    const float* ipg_base = g_inproj + sb2 * NPROJ + dir * NGATE + sg * HH + jt * 8 + sj4 * 4;

    float c_reg = 0.f;
    const int j = jt * 8 + w;

    for (int t = 0; t < TT; t++) {
        const int p  = t & 1;
        const int tt = dir ? (TT - 1 - t) : t;

        // prefetch step-invariant input projection BEFORE the barrier
        float4 ipv = *(const float4*)(ipg_base + (size_t)tt * 32 * NPROJ);

        if (t > 0) {
            __syncthreads();
            if (tid == 0) {
                __threadfence();
                unsigned a = atomicAdd(&g_bar_cnt[dir], 1u);
                if (a == 63u) {
                    g_bar_cnt[dir] = 0u;
                    __threadfence();
                    atomicExch(&g_bar_gen[dir], (unsigned)t);
                } else {
                    while (*(volatile unsigned*)&g_bar_gen[dir] < (unsigned)t) { }
                }
                __threadfence();
            }
            __syncthreads();
        }

        // ---- stage h(t-1) fp32 -> fp16 smem [b][k], pitch HP ----
        {
            const float* hsrc = g_h + (size_t)(p * 2 + dir) * (BB * HH);
            for (int i = tid; i < 2048; i += 256) {
                int bb = i >> 6, seg = i & 63;
                const float4* s4 = (const float4*)(hsrc + bb * 512 + seg * 8);
                float4 v0 = s4[0], v1 = s4[1];
                uint4 hv;
                hv.x = pack2h(v0.x, v0.y);
                hv.y = pack2h(v0.z, v0.w);
                hv.z = pack2h(v1.x, v1.y);
                hv.w = pack2h(v1.z, v1.w);
                *(uint4*)(lsm + OFF_H + (bb * HP + seg * 8) * 2) = hv;
            }
        }
        // ---- stage input projection ----
        {
            int rbase = sg * 8 + sj4 * 4;
            ips[(rbase + 0) * 33 + sb2] = ipv.x;
            ips[(rbase + 1) * 33 + sb2] = ipv.y;
            ips[(rbase + 2) * 33 + sb2] = ipv.z;
            ips[(rbase + 3) * 33 + sb2] = ipv.w;
        }
        __syncthreads();

        // ---- mma: C[b 16(mi)][r 8(ni)] over K=512, hi+lo products ----
        float ahe[4], aho[4], ale[4], alo4[4];
#pragma unroll
        for (int q = 0; q < 4; q++) { ahe[q] = 0.f; aho[q] = 0.f; ale[q] = 0.f; alo4[q] = 0.f; }

#pragma unroll
        for (int kt = 0; kt < 32; kt += 2) {
            uint32_t a0[4], a1[4], bh0[2], bh1[2], bl0[2], bl1[2];
            LDSM_X4(a0[0], a0[1], a0[2], a0[3], aoff + kt * 32);
            LDSM_X4(a1[0], a1[1], a1[2], a1[3], aoff + kt * 32 + 32);
            LDSM_X2(bh0[0], bh0[1], bhoff + kt * 32);
            LDSM_X2(bh1[0], bh1[1], bhoff + kt * 32 + 32);
            LDSM_X2(bl0[0], bl0[1], bloff + kt * 32);
            LDSM_X2(bl1[0], bl1[1], bloff + kt * 32 + 32);
            MMA_F16(ahe, a0, bh0);
            MMA_F16(aho, a1, bh1);
            MMA_F16(ale, a0, bl0);
            MMA_F16(alo4, a1, bl1);
        }

        // ---- epilogue: acc -> Cs[r][b] ----
        {
            int row0 = mi * 16 + (lane >> 2);       // b
            int col0 = ni * 8 + (lane & 3) * 2;     // r
            float d0 = ahe[0] + aho[0] + ale[0] + alo4[0];
            float d1 = ahe[1] + aho[1] + ale[1] + alo4[1];
            float d2 = ahe[2] + aho[2] + ale[2] + alo4[2];
            float d3 = ahe[3] + aho[3] + ale[3] + alo4[3];
            Cs[col0 * 33 + row0] = d0;
            Cs[(col0 + 1) * 33 + row0] = d1;
            Cs[col0 * 33 + row0 + 8] = d2;
            Cs[(col0 + 1) * 33 + row0 + 8] = d3;
        }
        __syncthreads();

        // ---- gate combine: thread (jl=w, b=lane) ----
        float gi = Cs[(0 * 8 + w) * 33 + b] + ips[(0 * 8 + w) * 33 + b];
        float gf = Cs[(1 * 8 + w) * 33 + b] + ips[(1 * 8 + w) * 33 + b];
        float gg = Cs[(2 * 8 + w) * 33 + b] + ips[(2 * 8 + w) * 33 + b];
        float go = Cs[(3 * 8 + w) * 33 + b] + ips[(3 * 8 + w) * 33 + b];

        gi = fast_sigmoid(gi);
        gf = fast_sigmoid(gf);
        gg = fast_tanh(gg);
        go = fast_sigmoid(go);

        c_reg = gf * c_reg + gi * gg;
        float h = go * fast_tanh(c_reg);

        g_h[(size_t)((p ^ 1) * 2 + dir) * (BB * HH) + b * 512 + j] = h;

        size_t o = ((size_t)tt * 32 + b) * 1024 + dir * HH + j;
        if (layer == 0) {
            g_h0[o] = __float2half_rn(h);
        } else {
            g_hout1[o] = h;
        }
    }
}

// -------------------- FC: logits[b][t][c] --------------------
__global__ void fc_kernel(const float* __restrict__ fcw, const float* __restrict__ fcb,
                          float* __restrict__ out) {
    int row = blockIdx.x;          // t*BB + b
    int t = row >> 5;
    int b = row & 31;
    int c = threadIdx.x >> 5;      // 0..23
    int lane = threadIdx.x & 31;

    const float4* h4 = (const float4*)(g_hout1 + (size_t)row * 1024);
    const float4* w4 = (const float4*)(fcw + (size_t)c * 1024);
    float s = 0.f;
#pragma unroll 4
    for (int k = lane; k < 256; k += 32) {
        float4 a = h4[k], w = w4[k];
        s += a.x * w.x + a.y * w.y + a.z * w.z + a.w * w.w;
    }
#pragma unroll
    for (int o = 16; o; o >>= 1) s += __shfl_xor_sync(0xffffffffu, s, o);
    if (lane == 0) out[((size_t)b * TT + t) * CC + c] = s + fcb[c];
}

// -------------------- CRF per-batch block --------------------
__global__ void crf_block(const float* __restrict__ em, const int* __restrict__ labels,
                          const float* __restrict__ st, const float* __restrict__ en,
                          const float* __restrict__ tr) {
    const int b = blockIdx.x;
    const int cn = threadIdx.x;    // 32 threads, 24 active for DP
    __shared__ float trs[24][25];
    __shared__ float alpha[25];
    __shared__ int   labs[TT];
    __shared__ float s_en[24], s_st[24];

    for (int i = cn; i < 576; i += 32) trs[i / 24][i % 24] = tr[i];
    if (cn < 24) { s_en[cn] = en[cn]; s_st[cn] = st[cn]; }
    for (int i = cn; i < TT; i += 32) labs[i] = labels[b * TT + i];
    __syncwarp();

    const float* emb_ = em + (size_t)b * TT * CC;
    if (cn < 24) alpha[cn] = s_st[cn] + emb_[cn];
    __syncwarp();

    for (int t = 1; t < TT; t++) {
        float anew = 0.f;
        if (cn < 24) {
            float m = -1e30f;
#pragma unroll
            for (int cp = 0; cp < 24; cp++) m = fmaxf(m, alpha[cp] + trs[cp][cn]);
            float s = 0.f;
#pragma unroll
            for (int cp = 0; cp < 24; cp++) s += __expf(alpha[cp] + trs[cp][cn] - m);
            anew = m + __logf(s) + emb_[t * CC + cn];
        }
        __syncwarp();
        if (cn < 24) alpha[cn] = anew;
        __syncwarp();
    }

    float gs = 0.f;
    for (int t = cn; t < TT; t += 32) {
        int tg = labs[t];
        gs += emb_[t * CC + tg];
        if (t > 0) gs += trs[labs[t - 1]][tg];
    }
#pragma unroll
    for (int o = 16; o; o >>= 1) gs += __shfl_xor_sync(0xffffffffu, gs, o);

    if (cn == 0) {
        float m = -1e30f;
        for (int c = 0; c < 24; c++) m = fmaxf(m, alpha[c] + s_en[c]);
        float s = 0.f;
        for (int c = 0; c < 24; c++) s += __expf(alpha[c] + s_en[c] - m);
        float logZ = m + __logf(s);
        float num = gs + s_st[labs[0]] + s_en[labs[TT - 1]];
        g_crf_partial[b] = logZ - num;
    }
}

__global__ void crf_final(float* __restrict__ loss_out) {
    if (threadIdx.x == 0) {
        float L = 0.f;
        for (int b = 0; b < BB; b++) L += g_crf_partial[b];
        loss_out[0] = L;   // -llh
    }
}

// -------------------- launch --------------------
extern "C" void kernel_launch(void* const* d_in, const int* in_sizes, int n_in,
                              void* d_out, int out_size) {
    const int*   x         = (const int*)d_in[0];
    const int*   labels    = (const int*)d_in[1];
    const float* emb       = (const float*)d_in[2];
    const float* w_ih      = (const float*)d_in[3];
    const float* w_hh      = (const float*)d_in[4];
    const float* b_ih      = (const float*)d_in[5];
    const float* b_hh      = (const float*)d_in[6];
    const float* fc_w      = (const float*)d_in[7];
    const float* fc_b      = (const float*)d_in[8];
    const float* crf_start = (const float*)d_in[9];
    const float* crf_end   = (const float*)d_in[10];
    const float* crf_trans = (const float*)d_in[11];
    float* out = (float*)d_out;

    (void)in_sizes; (void)n_in; (void)out_size;

    cudaFuncSetAttribute(lstm_layer_persist,
                         cudaFuncAttributeMaxDynamicSharedMemorySize, L2_SMEM);
    cudaFuncSetAttribute(gemm_mma,
                         cudaFuncAttributeMaxDynamicSharedMemorySize, GM_SMEM);

    // 1. embedding gather -> fp16
    gather_split<<<MROWS, 256>>>(x, emb);

    // 2. weight converts
    wconv<<<8192, 256>>>(w_ih);
    wconv_hh<<<4096, 256>>>(w_hh);

    // 3. per-layer: tensor-core input projection, then tensor-core recurrence
    for (int l = 0; l < 2; l++) {
        const float* bih_l = b_ih + (size_t)l * NPROJ;
        const float* bhh_l = b_hh + (size_t)l * NPROJ;

        gemm_mma<<<dim3(NPROJ / 128, MROWS / 128), 256, GM_SMEM>>>(l, bih_l, bhh_l);
        zero_state_kernel<<<256, 256>>>();
        lstm_layer_persist<<<128, 256, L2_SMEM>>>(l);
    }

    // 4. FC -> logits into d_out as [b][t][c]
    fc_kernel<<<MROWS, 768>>>(fc_w, fc_b, out);

    // 5. CRF loss -> d_out[B*T*C]
    crf_block<<<BB, 32>>>(out, labels, crf_start, crf_end, crf_trans);
    crf_final<<<1, 32>>>(out + (size_t)BB * TT * CC);
}